// round 12
// baseline (speedup 1.0000x reference)
#include <cuda_runtime.h>
#include <cuda_bf16.h>
#include <cstdint>

#define N_NODES 100000
#define N_GRAPHS 2000
#define CAP 128            // per-node bucket capacity (deg ~ Poisson(32), max ~66)
#define F1 64
#define F2 128
#define BN_EPS 1e-5f

// ------------------------- device scratch (no allocs allowed) ---------------
__device__ int   g_cnti[N_NODES];
__device__ int   g_bucket[(size_t)N_NODES * CAP];
__device__ float g_dinv[N_NODES];
__device__ __align__(16) float g_xs[(size_t)N_NODES * 16];    // x * dinv, padded 10->16
__device__ __align__(16) float g_aggx[(size_t)N_NODES * 16];  // aggregated xs
__device__ __align__(16) float g_a1s[(size_t)N_NODES * F1];   // relu(bn(conv1)) * dinv
__device__ __align__(16) float g_agg1[(size_t)N_NODES * F1];  // aggregated a1s
__device__ __align__(16) float g_out2[(size_t)N_NODES * F2];  // conv2 output (pre-BN)
__device__ float g_m1v[10];        // Σ_r aggx_r           (first moments)
__device__ float g_m1M[55];        // Σ_r aggx aggxᵀ (upper triangle)
__device__ float g_sc1[F1], g_sh1[F1];
__device__ float g_sum2[F2], g_sq2[F2];
__device__ float g_pool[N_GRAPHS * F2];
__device__ float g_cnt[N_GRAPHS];

#define FMA_F32X2(d, a, b, c) \
    asm("fma.rn.f32x2 %0, %1, %2, %3;" : "=l"(d) : "l"(a), "l"(b), "l"(c))
#define ADD_F32X2(d, a, b) \
    asm("add.rn.f32x2 %0, %1, %2;" : "=l"(d) : "l"(a), "l"(b))

__device__ __forceinline__ float2 unpack2(unsigned long long p) {
    unsigned int lo, hi;
    asm("mov.b64 {%0, %1}, %2;" : "=r"(lo), "=r"(hi) : "l"(p));
    return make_float2(__uint_as_float(lo), __uint_as_float(hi));
}

// ------------------------- kernels ------------------------------------------

__global__ void k_zero() {
    int i = blockIdx.x * blockDim.x + threadIdx.x;
    int stride = gridDim.x * blockDim.x;
    for (int j = i; j < N_NODES; j += stride) g_cnti[j] = 0;
    for (int j = i; j < N_GRAPHS * F2; j += stride) g_pool[j] = 0.f;
    for (int j = i; j < N_GRAPHS; j += stride) g_cnt[j] = 0.f;
    if (i < 10) g_m1v[i] = 0.f;
    if (i < 55) g_m1M[i] = 0.f;
    if (i < F2) { g_sum2[i] = 0.f; g_sq2[i] = 0.f; }
}

// Direct bucket fill.
__global__ void k_fill(const int* __restrict__ src, const int* __restrict__ dst, int E) {
    int i = blockIdx.x * blockDim.x + threadIdx.x;
    if (i >= E) return;
    int d = dst[i];
    int p = atomicAdd(&g_cnti[d], 1);
    if (p < CAP) g_bucket[(size_t)d * CAP + p] = src[i];
}

// dinv + xs = x*dinv (padded to 16 floats).
__global__ void k_prep(const float* __restrict__ x) {
    int r = blockIdx.x * blockDim.x + threadIdx.x;
    if (r >= N_NODES) return;
    float di = rsqrtf((float)g_cnti[r] + 1.0f);
    g_dinv[r] = di;
    const float* xr = x + (size_t)r * 10;
    float4* o = (float4*)(g_xs + (size_t)r * 16);
    o[0] = make_float4(xr[0] * di, xr[1] * di, xr[2] * di, xr[3] * di);
    o[1] = make_float4(xr[4] * di, xr[5] * di, xr[6] * di, xr[7] * di);
    o[2] = make_float4(xr[8] * di, xr[9] * di, 0.f, 0.f);
    o[3] = make_float4(0.f, 0.f, 0.f, 0.f);
}

// Aggregate xs (16 floats/row). 4 lanes x 16B per row (8 rows/warp), packed adds.
__global__ void __launch_bounds__(256) k_aggx() {
    int tid = threadIdx.x;
    int ql = tid & 3;
    unsigned qmask = 0xFu << ((tid & 31) & ~3);
    int gq = (blockIdx.x * blockDim.x + tid) >> 2;
    int nq = (gridDim.x * blockDim.x) >> 2;
    const ulonglong2* xs2 = (const ulonglong2*)g_xs;   // 4 x 16B per row
    float4* ag4 = (float4*)g_aggx;
    for (int row = gq; row < N_NODES; row += nq) {
        int deg = min(g_cnti[row], CAP);
        const int* bkt = g_bucket + (size_t)row * CAP;
        ulonglong2 acc = xs2[(size_t)row * 4 + ql];
        int e = 0;
        for (; e + 4 <= deg; e += 4) {
            int myidx = bkt[e + ql];
            int s0 = __shfl_sync(qmask, myidx, 0, 4);
            int s1 = __shfl_sync(qmask, myidx, 1, 4);
            int s2 = __shfl_sync(qmask, myidx, 2, 4);
            int s3 = __shfl_sync(qmask, myidx, 3, 4);
            ulonglong2 v0 = xs2[(size_t)s0 * 4 + ql];
            ulonglong2 v1 = xs2[(size_t)s1 * 4 + ql];
            ulonglong2 v2 = xs2[(size_t)s2 * 4 + ql];
            ulonglong2 v3 = xs2[(size_t)s3 * 4 + ql];
            ADD_F32X2(acc.x, acc.x, v0.x); ADD_F32X2(acc.y, acc.y, v0.y);
            ADD_F32X2(acc.x, acc.x, v1.x); ADD_F32X2(acc.y, acc.y, v1.y);
            ADD_F32X2(acc.x, acc.x, v2.x); ADD_F32X2(acc.y, acc.y, v2.y);
            ADD_F32X2(acc.x, acc.x, v3.x); ADD_F32X2(acc.y, acc.y, v3.y);
        }
        if (e < deg) {
            int n = deg - e;
            int myidx = (ql < n) ? bkt[e + ql] : 0;
            for (int j = 0; j < n; j++) {
                int s = __shfl_sync(qmask, myidx, j, 4);
                ulonglong2 v = xs2[(size_t)s * 4 + ql];
                ADD_F32X2(acc.x, acc.x, v.x);
                ADD_F32X2(acc.y, acc.y, v.y);
            }
        }
        float di = g_dinv[row];
        float2 lo = unpack2(acc.x), hi = unpack2(acc.y);
        ag4[(size_t)row * 4 + ql] =
            make_float4(lo.x * di, lo.y * di, hi.x * di, hi.y * di);
    }
}

// First+second moments of aggx (10-dim): s[10], M[55] (upper triangle).
__global__ void __launch_bounds__(256) k_mom() {
    float s[10], M[55];
#pragma unroll
    for (int i = 0; i < 10; i++) s[i] = 0.f;
#pragma unroll
    for (int i = 0; i < 55; i++) M[i] = 0.f;
    int stride = gridDim.x * blockDim.x;
    for (int r = blockIdx.x * blockDim.x + threadIdx.x; r < N_NODES; r += stride) {
        const float4* a = (const float4*)(g_aggx + (size_t)r * 16);
        float4 v0 = a[0], v1 = a[1], v2 = a[2];
        float v[10] = {v0.x, v0.y, v0.z, v0.w, v1.x, v1.y, v1.z, v1.w, v2.x, v2.y};
        int idx = 0;
#pragma unroll
        for (int i = 0; i < 10; i++) {
            s[i] += v[i];
#pragma unroll
            for (int j = i; j < 10; j++) M[idx++] += v[i] * v[j];
        }
    }
    // warp reduce then one atomic per warp
#pragma unroll
    for (int i = 0; i < 10; i++)
#pragma unroll
        for (int o = 16; o; o >>= 1) s[i] += __shfl_down_sync(0xffffffffu, s[i], o);
#pragma unroll
    for (int i = 0; i < 55; i++)
#pragma unroll
        for (int o = 16; o; o >>= 1) M[i] += __shfl_down_sync(0xffffffffu, M[i], o);
    if ((threadIdx.x & 31) == 0) {
#pragma unroll
        for (int i = 0; i < 10; i++) atomicAdd(&g_m1v[i], s[i]);
#pragma unroll
        for (int i = 0; i < 55; i++) atomicAdd(&g_m1M[i], M[i]);
    }
}

// BN1 scale/shift from moments: mu_f = s.w_f/N ; E[h^2]_f = w_f' M w_f / N.
__global__ void k_bnpar1(const float* __restrict__ W1,
                         const float* __restrict__ gam,
                         const float* __restrict__ bet) {
    int f = threadIdx.x;  // 0..63
    __shared__ float sv[10], sM[55];
    if (f < 10) sv[f] = g_m1v[f];
    if (f < 55) sM[f] = g_m1M[f];
    __syncthreads();
    float wf[10];
#pragma unroll
    for (int k = 0; k < 10; k++) wf[k] = W1[k * F1 + f];
    float s1 = 0.f, s2 = 0.f;
    int idx = 0;
#pragma unroll
    for (int k = 0; k < 10; k++) {
        s1 += sv[k] * wf[k];
#pragma unroll
        for (int l = k; l < 10; l++) {
            float m = sM[idx++];
            s2 += ((k == l) ? m : 2.f * m) * wf[k] * wf[l];
        }
    }
    float mu = s1 * (1.0f / N_NODES);
    float var = s2 * (1.0f / N_NODES) - mu * mu;
    float sc = gam[f] * rsqrtf(var + BN_EPS);
    g_sc1[f] = sc;
    g_sh1[f] = bet[f] - mu * sc;
}

// Fused layer-1: a1s = relu(bn1(aggx @ W1)) * dinv, no intermediate buffer.
__global__ void __launch_bounds__(256) k_l1fused(const float* __restrict__ W1) {
    __shared__ float Ws[10 * F1];
    __shared__ float xs[4][16];
    __shared__ float sc[F1], sh[F1];
    int tx = threadIdx.x;  // 0..63 feature
    int ty = threadIdx.y;  // 0..3 row
    int t = ty * 64 + tx;
    for (int j = t; j < 10 * F1; j += 256) Ws[j] = W1[j];
    if (t < F1) { sc[t] = g_sc1[t]; sh[t] = g_sh1[t]; }
    __syncthreads();
    for (int rb = blockIdx.x * 4; rb < N_NODES; rb += gridDim.x * 4) {
        if (t < 64) {
            int rr = rb + (t >> 4);
            xs[t >> 4][t & 15] = (rr < N_NODES) ? g_aggx[(size_t)rr * 16 + (t & 15)] : 0.f;
        }
        __syncthreads();
        int row = rb + ty;
        if (row < N_NODES) {
            float acc = 0.f;
#pragma unroll
            for (int k = 0; k < 10; k++) acc += xs[ty][k] * Ws[k * F1 + tx];
            g_a1s[(size_t)row * F1 + tx] =
                fmaxf(acc * sc[tx] + sh[tx], 0.f) * g_dinv[row];
        }
        __syncthreads();
    }
}

// Aggregate a1s (64 floats/row). 16 lanes x 16B per row (2 rows/warp), packed adds.
// agg1[d] = dinv[d] * (a1s[d] + sum_s a1s[s]).
__global__ void __launch_bounds__(256) k_agg1() {
    int tid = threadIdx.x;
    int hl = tid & 15;
    unsigned hmask = 0xFFFFu << ((tid & 31) & 16);
    int gh = (blockIdx.x * blockDim.x + tid) >> 4;
    int nh = (gridDim.x * blockDim.x) >> 4;
    const ulonglong2* a2 = (const ulonglong2*)g_a1s;   // 16 x 16B per row
    float4* o4 = (float4*)g_agg1;
    for (int row = gh; row < N_NODES; row += nh) {
        int deg = min(g_cnti[row], CAP);
        const int* bkt = g_bucket + (size_t)row * CAP;
        ulonglong2 acc = a2[(size_t)row * 16 + hl];
        int e = 0;
        while (e < deg) {
            int n = min(16, deg - e);
            int myidx = (hl < n) ? bkt[e + hl] : 0;
            e += n;
            int j = 0;
            for (; j + 4 <= n; j += 4) {
                int s0 = __shfl_sync(hmask, myidx, j, 16);
                int s1 = __shfl_sync(hmask, myidx, j + 1, 16);
                int s2 = __shfl_sync(hmask, myidx, j + 2, 16);
                int s3 = __shfl_sync(hmask, myidx, j + 3, 16);
                ulonglong2 v0 = a2[(size_t)s0 * 16 + hl];
                ulonglong2 v1 = a2[(size_t)s1 * 16 + hl];
                ulonglong2 v2 = a2[(size_t)s2 * 16 + hl];
                ulonglong2 v3 = a2[(size_t)s3 * 16 + hl];
                ADD_F32X2(acc.x, acc.x, v0.x); ADD_F32X2(acc.y, acc.y, v0.y);
                ADD_F32X2(acc.x, acc.x, v1.x); ADD_F32X2(acc.y, acc.y, v1.y);
                ADD_F32X2(acc.x, acc.x, v2.x); ADD_F32X2(acc.y, acc.y, v2.y);
                ADD_F32X2(acc.x, acc.x, v3.x); ADD_F32X2(acc.y, acc.y, v3.y);
            }
            for (; j < n; j++) {
                int s = __shfl_sync(hmask, myidx, j, 16);
                ulonglong2 v = a2[(size_t)s * 16 + hl];
                ADD_F32X2(acc.x, acc.x, v.x);
                ADD_F32X2(acc.y, acc.y, v.y);
            }
        }
        float di = g_dinv[row];
        float2 lo = unpack2(acc.x), hi = unpack2(acc.y);
        o4[(size_t)row * 16 + hl] =
            make_float4(lo.x * di, lo.y * di, hi.x * di, hi.y * di);
    }
}

// out2 = agg1 @ W2 via packed f32x2 (2 rows at once), fused BN2 stats.
__global__ void __launch_bounds__(128) k_gemm2b(const float* __restrict__ W2) {
    int tx = threadIdx.x;
    float w2[F1];
#pragma unroll
    for (int k = 0; k < F1; k++) w2[k] = W2[(size_t)k * F2 + tx];

    __shared__ float2 a_s[F1];   // .x = row r, .y = row r+1
    float lsum = 0.f, lsq = 0.f;

    for (int r = blockIdx.x * 2; r < N_NODES; r += gridDim.x * 2) {
        int lr = tx >> 6;
        int kk = tx & 63;
        int rr = r + lr;
        float av = (rr < N_NODES) ? g_agg1[(size_t)rr * F1 + kk] : 0.f;
        __syncthreads();
        if (lr == 0) a_s[kk].x = av; else a_s[kk].y = av;
        __syncthreads();

        unsigned long long accp = 0ULL;  // packed (0.f, 0.f)
        const unsigned long long* ap = (const unsigned long long*)a_s;
#pragma unroll
        for (int k = 0; k < F1; k++) {
            unsigned long long wp;
            asm("mov.b64 %0, {%1, %1};" : "=l"(wp) : "r"(__float_as_uint(w2[k])));
            FMA_F32X2(accp, ap[k], wp, accp);
        }
        float2 a01 = unpack2(accp);
        float acc0 = a01.x, acc1 = a01.y;

        g_out2[(size_t)r * F2 + tx] = acc0;
        lsum += acc0; lsq += acc0 * acc0;
        if (r + 1 < N_NODES) {
            g_out2[(size_t)(r + 1) * F2 + tx] = acc1;
            lsum += acc1; lsq += acc1 * acc1;
        }
    }
    atomicAdd(&g_sum2[tx], lsum);
    atomicAdd(&g_sq2[tx], lsq);
}

// Pooling: relu(bn2(out2)) segment-summed by sorted batch id. BN inline.
__global__ void k_pool(const int* __restrict__ batch,
                       const float* __restrict__ gam,
                       const float* __restrict__ bet) {
    int tx = threadIdx.x;  // 0..127
    float mu = g_sum2[tx] * (1.0f / N_NODES);
    float var = g_sq2[tx] * (1.0f / N_NODES) - mu * mu;
    float sc = gam[tx] * rsqrtf(var + BN_EPS);
    float sh = bet[tx] - mu * sc;

    int rpb = (N_NODES + gridDim.x - 1) / gridDim.x;
    int r0 = blockIdx.x * rpb;
    int r1 = min(r0 + rpb, N_NODES);
    if (r0 >= r1) return;
    int curb = batch[r0];
    float acc = 0.f, c = 0.f;
    for (int r = r0; r < r1; r++) {
        int b = batch[r];
        if (b != curb) {
            atomicAdd(&g_pool[curb * F2 + tx], acc);
            if (tx == 0) atomicAdd(&g_cnt[curb], c);
            acc = 0.f; c = 0.f;
            curb = b;
        }
        float v = g_out2[(size_t)r * F2 + tx];
        acc += fmaxf(v * sc + sh, 0.f);
        c += 1.f;
    }
    atomicAdd(&g_pool[curb * F2 + tx], acc);
    if (tx == 0) atomicAdd(&g_cnt[curb], c);
}

// Final MLP head. One block (64 threads) per graph.
__global__ void k_mlp(const float* __restrict__ fW1, const float* __restrict__ fb1,
                      const float* __restrict__ fW2, const float* __restrict__ fb2,
                      float* __restrict__ out) {
    int g = blockIdx.x;
    int tx = threadIdx.x;  // 0..63
    __shared__ float prow[F2];
    __shared__ float partial[2];
    float c = fmaxf(g_cnt[g], 1.0f);
    float inv = 1.0f / c;
    prow[tx] = g_pool[g * F2 + tx] * inv;
    prow[tx + 64] = g_pool[g * F2 + tx + 64] * inv;
    __syncthreads();
    float h = fb1[tx];
#pragma unroll 8
    for (int k = 0; k < F2; k++) h += prow[k] * fW1[(size_t)k * 64 + tx];
    h = fmaxf(h, 0.f);
    float p = h * fW2[tx];
#pragma unroll
    for (int off = 16; off; off >>= 1) p += __shfl_down_sync(0xffffffff, p, off);
    if ((tx & 31) == 0) partial[tx >> 5] = p;
    __syncthreads();
    if (tx == 0) out[g] = partial[0] + partial[1] + fb2[0];
}

// ------------------------- launch --------------------------------------------
extern "C" void kernel_launch(void* const* d_in, const int* in_sizes, int n_in,
                              void* d_out, int out_size) {
    const float* x   = (const float*)d_in[0];
    const int*   src = (const int*)d_in[1];
    const int*   dst = (const int*)d_in[2];
    const int*   bat = (const int*)d_in[3];
    const float* W1  = (const float*)d_in[4];
    // d_in[5] = b1 (cancels in BN)
    const float* g1  = (const float*)d_in[6];
    const float* be1 = (const float*)d_in[7];
    const float* W2  = (const float*)d_in[8];
    // d_in[9] = b2 (cancels in BN)
    const float* g2  = (const float*)d_in[10];
    const float* be2 = (const float*)d_in[11];
    const float* fW1 = (const float*)d_in[12];
    const float* fb1 = (const float*)d_in[13];
    const float* fW2 = (const float*)d_in[14];
    const float* fb2 = (const float*)d_in[15];
    float* out = (float*)d_out;

    int E = in_sizes[1];

    k_zero<<<512, 256>>>();
    k_fill<<<(E + 255) / 256, 256>>>(src, dst, E);
    k_prep<<<(N_NODES + 255) / 256, 256>>>(x);

    k_aggx<<<888, 256>>>();
    k_mom<<<64, 256>>>();
    k_bnpar1<<<1, 64>>>(W1, g1, be1);
    k_l1fused<<<2048, dim3(64, 4)>>>(W1);

    k_agg1<<<888, 256>>>();
    k_gemm2b<<<2048, 128>>>(W2);

    k_pool<<<1024, 128>>>(bat, g2, be2);
    k_mlp<<<N_GRAPHS, 64>>>(fW1, fb1, fW2, fb2, out);
}

// round 13
// speedup vs baseline: 1.1912x; 1.1912x over previous
#include <cuda_runtime.h>
#include <cuda_bf16.h>
#include <cstdint>

#define N_NODES 100000
#define N_GRAPHS 2000
#define CAP 128            // per-node bucket capacity (deg ~ Poisson(32), max ~66)
#define F1 64
#define F2 128
#define BN_EPS 1e-5f

// ------------------------- device scratch (no allocs allowed) ---------------
__device__ int   g_cnti[N_NODES];
__device__ int   g_bucket[(size_t)N_NODES * CAP];
__device__ float g_dinv[N_NODES];
__device__ __align__(16) float g_xs[(size_t)N_NODES * 16];    // x * dinv, padded 10->16
__device__ __align__(16) float g_aggx[(size_t)N_NODES * 16];  // aggregated xs
__device__ __align__(16) float g_out1[(size_t)N_NODES * F1];  // conv1 output (pre-BN)
__device__ __align__(16) float g_a1s[(size_t)N_NODES * F1];   // relu(bn(conv1)) * dinv
__device__ __align__(16) float g_agg1[(size_t)N_NODES * F1];  // aggregated a1s
__device__ __align__(16) float g_out2[(size_t)N_NODES * F2];  // conv2 output (pre-BN)
__device__ float g_sum1[F1], g_sq1[F1];
__device__ float g_sum2[F2], g_sq2[F2];

#define FMA_F32X2(d, a, b, c) \
    asm("fma.rn.f32x2 %0, %1, %2, %3;" : "=l"(d) : "l"(a), "l"(b), "l"(c))
#define ADD_F32X2(d, a, b) \
    asm("add.rn.f32x2 %0, %1, %2;" : "=l"(d) : "l"(a), "l"(b))

__device__ __forceinline__ float2 unpack2(unsigned long long p) {
    unsigned int lo, hi;
    asm("mov.b64 {%0, %1}, %2;" : "=r"(lo), "=r"(hi) : "l"(p));
    return make_float2(__uint_as_float(lo), __uint_as_float(hi));
}

// first index i in [0,N_NODES) with batch[i] >= key (batch sorted ascending)
__device__ __forceinline__ int lower_bound_batch(const int* __restrict__ batch, int key) {
    int lo = 0, hi = N_NODES;
    while (lo < hi) {
        int mid = (lo + hi) >> 1;
        if (batch[mid] < key) lo = mid + 1; else hi = mid;
    }
    return lo;
}

// ------------------------- kernels ------------------------------------------

__global__ void k_zero() {
    int i = blockIdx.x * blockDim.x + threadIdx.x;
    int stride = gridDim.x * blockDim.x;
    for (int j = i; j < N_NODES; j += stride) g_cnti[j] = 0;
    if (i < F1) { g_sum1[i] = 0.f; g_sq1[i] = 0.f; }
    if (i < F2) { g_sum2[i] = 0.f; g_sq2[i] = 0.f; }
}

// Direct bucket fill.
__global__ void k_fill(const int* __restrict__ src, const int* __restrict__ dst, int E) {
    int i = blockIdx.x * blockDim.x + threadIdx.x;
    if (i >= E) return;
    int d = dst[i];
    int p = atomicAdd(&g_cnti[d], 1);
    if (p < CAP) g_bucket[(size_t)d * CAP + p] = src[i];
}

// dinv + xs = x*dinv (padded to 16 floats).
__global__ void k_prep(const float* __restrict__ x) {
    int r = blockIdx.x * blockDim.x + threadIdx.x;
    if (r >= N_NODES) return;
    float di = rsqrtf((float)g_cnti[r] + 1.0f);
    g_dinv[r] = di;
    const float* xr = x + (size_t)r * 10;
    float4* o = (float4*)(g_xs + (size_t)r * 16);
    o[0] = make_float4(xr[0] * di, xr[1] * di, xr[2] * di, xr[3] * di);
    o[1] = make_float4(xr[4] * di, xr[5] * di, xr[6] * di, xr[7] * di);
    o[2] = make_float4(xr[8] * di, xr[9] * di, 0.f, 0.f);
    o[3] = make_float4(0.f, 0.f, 0.f, 0.f);
}

// Aggregate xs (16 floats/row). 4 lanes x 16B per row (8 rows/warp), packed adds.
__global__ void __launch_bounds__(256) k_aggx() {
    int tid = threadIdx.x;
    int ql = tid & 3;
    unsigned qmask = 0xFu << ((tid & 31) & ~3);
    int gq = (blockIdx.x * blockDim.x + tid) >> 2;
    int nq = (gridDim.x * blockDim.x) >> 2;
    const ulonglong2* xs2 = (const ulonglong2*)g_xs;   // 4 x 16B per row
    float4* ag4 = (float4*)g_aggx;
    for (int row = gq; row < N_NODES; row += nq) {
        int c = g_cnti[row];
        int deg = min(c, CAP);
        float di = rsqrtf((float)c + 1.0f);
        const int* bkt = g_bucket + (size_t)row * CAP;
        ulonglong2 acc = xs2[(size_t)row * 4 + ql];
        int e = 0;
        for (; e + 4 <= deg; e += 4) {
            int myidx = bkt[e + ql];
            int s0 = __shfl_sync(qmask, myidx, 0, 4);
            int s1 = __shfl_sync(qmask, myidx, 1, 4);
            int s2 = __shfl_sync(qmask, myidx, 2, 4);
            int s3 = __shfl_sync(qmask, myidx, 3, 4);
            ulonglong2 v0 = xs2[(size_t)s0 * 4 + ql];
            ulonglong2 v1 = xs2[(size_t)s1 * 4 + ql];
            ulonglong2 v2 = xs2[(size_t)s2 * 4 + ql];
            ulonglong2 v3 = xs2[(size_t)s3 * 4 + ql];
            ADD_F32X2(acc.x, acc.x, v0.x); ADD_F32X2(acc.y, acc.y, v0.y);
            ADD_F32X2(acc.x, acc.x, v1.x); ADD_F32X2(acc.y, acc.y, v1.y);
            ADD_F32X2(acc.x, acc.x, v2.x); ADD_F32X2(acc.y, acc.y, v2.y);
            ADD_F32X2(acc.x, acc.x, v3.x); ADD_F32X2(acc.y, acc.y, v3.y);
        }
        if (e < deg) {
            int n = deg - e;
            int myidx = (ql < n) ? bkt[e + ql] : 0;
            for (int j = 0; j < n; j++) {
                int s = __shfl_sync(qmask, myidx, j, 4);
                ulonglong2 v = xs2[(size_t)s * 4 + ql];
                ADD_F32X2(acc.x, acc.x, v.x);
                ADD_F32X2(acc.y, acc.y, v.y);
            }
        }
        float2 lo = unpack2(acc.x), hi = unpack2(acc.y);
        ag4[(size_t)row * 4 + ql] =
            make_float4(lo.x * di, lo.y * di, hi.x * di, hi.y * di);
    }
}

// out1 = aggx[:, :10] @ W1, fused BN1 stats. Block: 64 (features) x 4 (rows).
__global__ void __launch_bounds__(256) k_gemm1b(const float* __restrict__ W1) {
    __shared__ float Ws[10 * F1];
    __shared__ float xs[4][16];
    __shared__ float s_sum[F1], s_sq[F1];
    int tx = threadIdx.x;  // 0..63 feature
    int ty = threadIdx.y;  // 0..3 row
    int t = ty * 64 + tx;
    for (int j = t; j < 10 * F1; j += 256) Ws[j] = W1[j];
    if (t < F1) { s_sum[t] = 0.f; s_sq[t] = 0.f; }
    __syncthreads();
    float lsum = 0.f, lsq = 0.f;
    for (int rb = blockIdx.x * 4; rb < N_NODES; rb += gridDim.x * 4) {
        if (t < 64) {
            int rr = rb + (t >> 4);
            xs[t >> 4][t & 15] = (rr < N_NODES) ? g_aggx[(size_t)rr * 16 + (t & 15)] : 0.f;
        }
        __syncthreads();
        int row = rb + ty;
        if (row < N_NODES) {
            float acc = 0.f;
#pragma unroll
            for (int k = 0; k < 10; k++) acc += xs[ty][k] * Ws[k * F1 + tx];
            g_out1[(size_t)row * F1 + tx] = acc;
            lsum += acc;
            lsq += acc * acc;
        }
        __syncthreads();
    }
    atomicAdd(&s_sum[tx], lsum);
    atomicAdd(&s_sq[tx], lsq);
    __syncthreads();
    if (t < F1) {
        atomicAdd(&g_sum1[t], s_sum[t]);
        atomicAdd(&g_sq1[t], s_sq[t]);
    }
}

// a1s = relu(bn1(out1)) * dinv. Elementwise, float4-vectorized.
__global__ void __launch_bounds__(256) k_mid(const float* __restrict__ gam,
                                             const float* __restrict__ bet) {
    __shared__ float sc[F1], sh[F1];
    int tid = threadIdx.x;
    if (tid < F1) {
        float mu = g_sum1[tid] * (1.0f / N_NODES);
        float var = g_sq1[tid] * (1.0f / N_NODES) - mu * mu;
        float s = gam[tid] * rsqrtf(var + BN_EPS);
        sc[tid] = s;
        sh[tid] = bet[tid] - mu * s;
    }
    __syncthreads();
    const float4* in = (const float4*)g_out1;
    float4* outp = (float4*)g_a1s;
    int total = N_NODES * F1 / 4;
    for (int i = blockIdx.x * blockDim.x + tid; i < total; i += gridDim.x * blockDim.x) {
        int row = i >> 4;           // 16 float4 per row
        int f = (i & 15) * 4;
        float di = g_dinv[row];
        float4 v = in[i];
        float4 o;
        o.x = fmaxf(v.x * sc[f + 0] + sh[f + 0], 0.f) * di;
        o.y = fmaxf(v.y * sc[f + 1] + sh[f + 1], 0.f) * di;
        o.z = fmaxf(v.z * sc[f + 2] + sh[f + 2], 0.f) * di;
        o.w = fmaxf(v.w * sc[f + 3] + sh[f + 3], 0.f) * di;
        outp[i] = o;
    }
}

// Aggregate a1s (64 floats/row). 16 lanes x 16B per row (2 rows/warp), packed adds.
// agg1[d] = dinv[d] * (a1s[d] + sum_s a1s[s]).
__global__ void __launch_bounds__(256) k_agg1() {
    int tid = threadIdx.x;
    int hl = tid & 15;
    unsigned hmask = 0xFFFFu << ((tid & 31) & 16);
    int gh = (blockIdx.x * blockDim.x + tid) >> 4;
    int nh = (gridDim.x * blockDim.x) >> 4;
    const ulonglong2* a2 = (const ulonglong2*)g_a1s;   // 16 x 16B per row
    float4* o4 = (float4*)g_agg1;
    for (int row = gh; row < N_NODES; row += nh) {
        int c = g_cnti[row];
        int deg = min(c, CAP);
        float di = rsqrtf((float)c + 1.0f);
        const int* bkt = g_bucket + (size_t)row * CAP;
        ulonglong2 acc = a2[(size_t)row * 16 + hl];
        int e = 0;
        while (e < deg) {
            int n = min(16, deg - e);
            int myidx = (hl < n) ? bkt[e + hl] : 0;
            e += n;
            int j = 0;
            for (; j + 4 <= n; j += 4) {
                int s0 = __shfl_sync(hmask, myidx, j, 16);
                int s1 = __shfl_sync(hmask, myidx, j + 1, 16);
                int s2 = __shfl_sync(hmask, myidx, j + 2, 16);
                int s3 = __shfl_sync(hmask, myidx, j + 3, 16);
                ulonglong2 v0 = a2[(size_t)s0 * 16 + hl];
                ulonglong2 v1 = a2[(size_t)s1 * 16 + hl];
                ulonglong2 v2 = a2[(size_t)s2 * 16 + hl];
                ulonglong2 v3 = a2[(size_t)s3 * 16 + hl];
                ADD_F32X2(acc.x, acc.x, v0.x); ADD_F32X2(acc.y, acc.y, v0.y);
                ADD_F32X2(acc.x, acc.x, v1.x); ADD_F32X2(acc.y, acc.y, v1.y);
                ADD_F32X2(acc.x, acc.x, v2.x); ADD_F32X2(acc.y, acc.y, v2.y);
                ADD_F32X2(acc.x, acc.x, v3.x); ADD_F32X2(acc.y, acc.y, v3.y);
            }
            for (; j < n; j++) {
                int s = __shfl_sync(hmask, myidx, j, 16);
                ulonglong2 v = a2[(size_t)s * 16 + hl];
                ADD_F32X2(acc.x, acc.x, v.x);
                ADD_F32X2(acc.y, acc.y, v.y);
            }
        }
        float2 lo = unpack2(acc.x), hi = unpack2(acc.y);
        o4[(size_t)row * 16 + hl] =
            make_float4(lo.x * di, lo.y * di, hi.x * di, hi.y * di);
    }
}

// out2 = agg1 @ W2 via packed f32x2 (2 rows at once), fused BN2 stats.
__global__ void __launch_bounds__(128) k_gemm2b(const float* __restrict__ W2) {
    int tx = threadIdx.x;
    float w2[F1];
#pragma unroll
    for (int k = 0; k < F1; k++) w2[k] = W2[(size_t)k * F2 + tx];

    __shared__ float2 a_s[F1];   // .x = row r, .y = row r+1
    float lsum = 0.f, lsq = 0.f;

    for (int r = blockIdx.x * 2; r < N_NODES; r += gridDim.x * 2) {
        int lr = tx >> 6;
        int kk = tx & 63;
        int rr = r + lr;
        float av = (rr < N_NODES) ? g_agg1[(size_t)rr * F1 + kk] : 0.f;
        __syncthreads();
        if (lr == 0) a_s[kk].x = av; else a_s[kk].y = av;
        __syncthreads();

        unsigned long long accp = 0ULL;  // packed (0.f, 0.f)
        const unsigned long long* ap = (const unsigned long long*)a_s;
#pragma unroll
        for (int k = 0; k < F1; k++) {
            unsigned long long wp;
            asm("mov.b64 %0, {%1, %1};" : "=l"(wp) : "r"(__float_as_uint(w2[k])));
            FMA_F32X2(accp, ap[k], wp, accp);
        }
        float2 a01 = unpack2(accp);
        float acc0 = a01.x, acc1 = a01.y;

        g_out2[(size_t)r * F2 + tx] = acc0;
        lsum += acc0; lsq += acc0 * acc0;
        if (r + 1 < N_NODES) {
            g_out2[(size_t)(r + 1) * F2 + tx] = acc1;
            lsum += acc1; lsq += acc1 * acc1;
        }
    }
    atomicAdd(&g_sum2[tx], lsum);
    atomicAdd(&g_sq2[tx], lsq);
}

// Fused pool + MLP head: one block per graph. batch is sorted, so graph g's
// node range is found by binary search — no atomics, no g_pool buffer.
__global__ void __launch_bounds__(128) k_poolmlp(
    const int* __restrict__ batch,
    const float* __restrict__ gam, const float* __restrict__ bet,
    const float* __restrict__ fW1, const float* __restrict__ fb1,
    const float* __restrict__ fW2, const float* __restrict__ fb2,
    float* __restrict__ out) {
    int g = blockIdx.x;
    int tx = threadIdx.x;  // 0..127 feature
    // BN2 params for my feature
    float mu = g_sum2[tx] * (1.0f / N_NODES);
    float var = g_sq2[tx] * (1.0f / N_NODES) - mu * mu;
    float sc = gam[tx] * rsqrtf(var + BN_EPS);
    float sh = bet[tx] - mu * sc;

    int lo = lower_bound_batch(batch, g);
    int hi = lower_bound_batch(batch, g + 1);

    float acc = 0.f;
    for (int r = lo; r < hi; r++) {
        float v = g_out2[(size_t)r * F2 + tx];
        acc += fmaxf(v * sc + sh, 0.f);
    }
    float cnt = fmaxf((float)(hi - lo), 1.0f);
    __shared__ float prow[F2];
    __shared__ float partial[2];
    prow[tx] = acc / cnt;
    __syncthreads();

    if (tx < 64) {
        float h = fb1[tx];
#pragma unroll 8
        for (int k = 0; k < F2; k++) h += prow[k] * fW1[(size_t)k * 64 + tx];
        h = fmaxf(h, 0.f);
        float p = h * fW2[tx];
#pragma unroll
        for (int off = 16; off; off >>= 1) p += __shfl_down_sync(0xffffffffu, p, off);
        if ((tx & 31) == 0) partial[tx >> 5] = p;
    }
    __syncthreads();
    if (tx == 0) out[g] = partial[0] + partial[1] + fb2[0];
}

// ------------------------- launch --------------------------------------------
extern "C" void kernel_launch(void* const* d_in, const int* in_sizes, int n_in,
                              void* d_out, int out_size) {
    const float* x   = (const float*)d_in[0];
    const int*   src = (const int*)d_in[1];
    const int*   dst = (const int*)d_in[2];
    const int*   bat = (const int*)d_in[3];
    const float* W1  = (const float*)d_in[4];
    // d_in[5] = b1 (cancels in BN)
    const float* g1  = (const float*)d_in[6];
    const float* be1 = (const float*)d_in[7];
    const float* W2  = (const float*)d_in[8];
    // d_in[9] = b2 (cancels in BN)
    const float* g2  = (const float*)d_in[10];
    const float* be2 = (const float*)d_in[11];
    const float* fW1 = (const float*)d_in[12];
    const float* fb1 = (const float*)d_in[13];
    const float* fW2 = (const float*)d_in[14];
    const float* fb2 = (const float*)d_in[15];
    float* out = (float*)d_out;

    int E = in_sizes[1];

    k_zero<<<512, 256>>>();
    k_fill<<<(E + 255) / 256, 256>>>(src, dst, E);
    k_prep<<<(N_NODES + 255) / 256, 256>>>(x);

    k_aggx<<<888, 256>>>();
    k_gemm1b<<<2048, dim3(64, 4)>>>(W1);
    k_mid<<<2048, 256>>>(g1, be1);

    k_agg1<<<888, 256>>>();
    k_gemm2b<<<2048, 128>>>(W2);

    k_poolmlp<<<N_GRAPHS, 128>>>(bat, g2, be2, fW1, fb1, fW2, fb2, out);
}

// round 14
// speedup vs baseline: 1.2156x; 1.0204x over previous
#include <cuda_runtime.h>
#include <cuda_bf16.h>
#include <cstdint>

#define N_NODES 100000
#define N_GRAPHS 2000
#define CAP 128            // per-node bucket capacity (deg ~ Poisson(32), max ~66)
#define F1 64
#define F2 128
#define BN_EPS 1e-5f

// ------------------------- device scratch (no allocs allowed) ---------------
__device__ int   g_cnti[N_NODES];
__device__ int   g_bucket[(size_t)N_NODES * CAP];
__device__ float g_dinv[N_NODES];
__device__ __align__(16) float g_xs[(size_t)N_NODES * 16];    // x * dinv, padded 10->16
__device__ __align__(16) float g_aggx[(size_t)N_NODES * 16];  // aggregated xs
__device__ __align__(16) float g_out1[(size_t)N_NODES * F1];  // conv1 output (pre-BN)
__device__ __align__(16) float g_a1s[(size_t)N_NODES * F1];   // relu(bn(conv1)) * dinv
__device__ __align__(16) float g_agg1[(size_t)N_NODES * F1];  // aggregated a1s
__device__ __align__(16) float g_out2[(size_t)N_NODES * F2];  // conv2 output (pre-BN)
__device__ float g_sum1[F1], g_sq1[F1];
__device__ float g_sum2[F2], g_sq2[F2];

#define FMA_F32X2(d, a, b, c) \
    asm("fma.rn.f32x2 %0, %1, %2, %3;" : "=l"(d) : "l"(a), "l"(b), "l"(c))
#define ADD_F32X2(d, a, b) \
    asm("add.rn.f32x2 %0, %1, %2;" : "=l"(d) : "l"(a), "l"(b))

__device__ __forceinline__ float2 unpack2(unsigned long long p) {
    unsigned int lo, hi;
    asm("mov.b64 {%0, %1}, %2;" : "=r"(lo), "=r"(hi) : "l"(p));
    return make_float2(__uint_as_float(lo), __uint_as_float(hi));
}

// first index i in [0,N_NODES) with batch[i] >= key (batch sorted ascending)
__device__ __forceinline__ int lower_bound_batch(const int* __restrict__ batch, int key) {
    int lo = 0, hi = N_NODES;
    while (lo < hi) {
        int mid = (lo + hi) >> 1;
        if (batch[mid] < key) lo = mid + 1; else hi = mid;
    }
    return lo;
}

// ------------------------- kernels ------------------------------------------

__global__ void k_zero() {
    int i = blockIdx.x * blockDim.x + threadIdx.x;
    int stride = gridDim.x * blockDim.x;
    for (int j = i; j < N_NODES; j += stride) g_cnti[j] = 0;
    if (i < F1) { g_sum1[i] = 0.f; g_sq1[i] = 0.f; }
    if (i < F2) { g_sum2[i] = 0.f; g_sq2[i] = 0.f; }
}

// Direct bucket fill, 4 edges/thread for MLP on the ATOMG+store chains.
__global__ void k_fill(const int* __restrict__ src, const int* __restrict__ dst, int E) {
    int i = blockIdx.x * blockDim.x + threadIdx.x;
    int E4 = E >> 2;
    if (i < E4) {
        int4 s = ((const int4*)src)[i];
        int4 d = ((const int4*)dst)[i];
        int p0 = atomicAdd(&g_cnti[d.x], 1);
        int p1 = atomicAdd(&g_cnti[d.y], 1);
        int p2 = atomicAdd(&g_cnti[d.z], 1);
        int p3 = atomicAdd(&g_cnti[d.w], 1);
        if (p0 < CAP) g_bucket[(size_t)d.x * CAP + p0] = s.x;
        if (p1 < CAP) g_bucket[(size_t)d.y * CAP + p1] = s.y;
        if (p2 < CAP) g_bucket[(size_t)d.z * CAP + p2] = s.z;
        if (p3 < CAP) g_bucket[(size_t)d.w * CAP + p3] = s.w;
    } else if (i == E4) {  // tail (E % 4 edges)
        for (int j = E4 * 4; j < E; j++) {
            int d = dst[j];
            int p = atomicAdd(&g_cnti[d], 1);
            if (p < CAP) g_bucket[(size_t)d * CAP + p] = src[j];
        }
    }
}

// dinv + xs = x*dinv (padded to 16 floats).
__global__ void k_prep(const float* __restrict__ x) {
    int r = blockIdx.x * blockDim.x + threadIdx.x;
    if (r >= N_NODES) return;
    float di = rsqrtf((float)g_cnti[r] + 1.0f);
    g_dinv[r] = di;
    const float* xr = x + (size_t)r * 10;
    float4* o = (float4*)(g_xs + (size_t)r * 16);
    o[0] = make_float4(xr[0] * di, xr[1] * di, xr[2] * di, xr[3] * di);
    o[1] = make_float4(xr[4] * di, xr[5] * di, xr[6] * di, xr[7] * di);
    o[2] = make_float4(xr[8] * di, xr[9] * di, 0.f, 0.f);
    o[3] = make_float4(0.f, 0.f, 0.f, 0.f);
}

// Aggregate xs (16 floats/row). 4 lanes x 16B per row (8 rows/warp), packed adds.
__global__ void __launch_bounds__(256) k_aggx() {
    int tid = threadIdx.x;
    int ql = tid & 3;
    unsigned qmask = 0xFu << ((tid & 31) & ~3);
    int gq = (blockIdx.x * blockDim.x + tid) >> 2;
    int nq = (gridDim.x * blockDim.x) >> 2;
    const ulonglong2* xs2 = (const ulonglong2*)g_xs;   // 4 x 16B per row
    float4* ag4 = (float4*)g_aggx;
    for (int row = gq; row < N_NODES; row += nq) {
        int c = g_cnti[row];
        int deg = min(c, CAP);
        float di = rsqrtf((float)c + 1.0f);
        const int* bkt = g_bucket + (size_t)row * CAP;
        ulonglong2 acc = xs2[(size_t)row * 4 + ql];
        int e = 0;
        for (; e + 4 <= deg; e += 4) {
            int myidx = bkt[e + ql];
            int s0 = __shfl_sync(qmask, myidx, 0, 4);
            int s1 = __shfl_sync(qmask, myidx, 1, 4);
            int s2 = __shfl_sync(qmask, myidx, 2, 4);
            int s3 = __shfl_sync(qmask, myidx, 3, 4);
            ulonglong2 v0 = xs2[(size_t)s0 * 4 + ql];
            ulonglong2 v1 = xs2[(size_t)s1 * 4 + ql];
            ulonglong2 v2 = xs2[(size_t)s2 * 4 + ql];
            ulonglong2 v3 = xs2[(size_t)s3 * 4 + ql];
            ADD_F32X2(acc.x, acc.x, v0.x); ADD_F32X2(acc.y, acc.y, v0.y);
            ADD_F32X2(acc.x, acc.x, v1.x); ADD_F32X2(acc.y, acc.y, v1.y);
            ADD_F32X2(acc.x, acc.x, v2.x); ADD_F32X2(acc.y, acc.y, v2.y);
            ADD_F32X2(acc.x, acc.x, v3.x); ADD_F32X2(acc.y, acc.y, v3.y);
        }
        if (e < deg) {
            int n = deg - e;
            int myidx = (ql < n) ? bkt[e + ql] : 0;
            for (int j = 0; j < n; j++) {
                int s = __shfl_sync(qmask, myidx, j, 4);
                ulonglong2 v = xs2[(size_t)s * 4 + ql];
                ADD_F32X2(acc.x, acc.x, v.x);
                ADD_F32X2(acc.y, acc.y, v.y);
            }
        }
        float2 lo = unpack2(acc.x), hi = unpack2(acc.y);
        ag4[(size_t)row * 4 + ql] =
            make_float4(lo.x * di, lo.y * di, hi.x * di, hi.y * di);
    }
}

// out1 = aggx[:, :10] @ W1, fused BN1 stats. Block: 64 (features) x 4 (rows),
// 8 rows per iteration (2 per ty) to halve sync overhead.
__global__ void __launch_bounds__(256) k_gemm1b(const float* __restrict__ W1) {
    __shared__ float Ws[10 * F1];
    __shared__ float xs[8][16];
    __shared__ float s_sum[F1], s_sq[F1];
    int tx = threadIdx.x;  // 0..63 feature
    int ty = threadIdx.y;  // 0..3
    int t = ty * 64 + tx;
    for (int j = t; j < 10 * F1; j += 256) Ws[j] = W1[j];
    if (t < F1) { s_sum[t] = 0.f; s_sq[t] = 0.f; }
    __syncthreads();
    float lsum = 0.f, lsq = 0.f;
    for (int rb = blockIdx.x * 8; rb < N_NODES; rb += gridDim.x * 8) {
        if (t < 128) {
            int rr = rb + (t >> 4);
            xs[t >> 4][t & 15] = (rr < N_NODES) ? g_aggx[(size_t)rr * 16 + (t & 15)] : 0.f;
        }
        __syncthreads();
        int row0 = rb + ty;
        int row1 = rb + ty + 4;
        float acc0 = 0.f, acc1 = 0.f;
#pragma unroll
        for (int k = 0; k < 10; k++) {
            float w = Ws[k * F1 + tx];
            acc0 += xs[ty][k] * w;
            acc1 += xs[ty + 4][k] * w;
        }
        if (row0 < N_NODES) {
            g_out1[(size_t)row0 * F1 + tx] = acc0;
            lsum += acc0; lsq += acc0 * acc0;
        }
        if (row1 < N_NODES) {
            g_out1[(size_t)row1 * F1 + tx] = acc1;
            lsum += acc1; lsq += acc1 * acc1;
        }
        __syncthreads();
    }
    atomicAdd(&s_sum[tx], lsum);
    atomicAdd(&s_sq[tx], lsq);
    __syncthreads();
    if (t < F1) {
        atomicAdd(&g_sum1[t], s_sum[t]);
        atomicAdd(&g_sq1[t], s_sq[t]);
    }
}

// a1s = relu(bn1(out1)) * dinv. Elementwise, float4-vectorized.
__global__ void __launch_bounds__(256) k_mid(const float* __restrict__ gam,
                                             const float* __restrict__ bet) {
    __shared__ float sc[F1], sh[F1];
    int tid = threadIdx.x;
    if (tid < F1) {
        float mu = g_sum1[tid] * (1.0f / N_NODES);
        float var = g_sq1[tid] * (1.0f / N_NODES) - mu * mu;
        float s = gam[tid] * rsqrtf(var + BN_EPS);
        sc[tid] = s;
        sh[tid] = bet[tid] - mu * s;
    }
    __syncthreads();
    const float4* in = (const float4*)g_out1;
    float4* outp = (float4*)g_a1s;
    int total = N_NODES * F1 / 4;
    for (int i = blockIdx.x * blockDim.x + tid; i < total; i += gridDim.x * blockDim.x) {
        int row = i >> 4;           // 16 float4 per row
        int f = (i & 15) * 4;
        float di = g_dinv[row];
        float4 v = in[i];
        float4 o;
        o.x = fmaxf(v.x * sc[f + 0] + sh[f + 0], 0.f) * di;
        o.y = fmaxf(v.y * sc[f + 1] + sh[f + 1], 0.f) * di;
        o.z = fmaxf(v.z * sc[f + 2] + sh[f + 2], 0.f) * di;
        o.w = fmaxf(v.w * sc[f + 3] + sh[f + 3], 0.f) * di;
        outp[i] = o;
    }
}

// Aggregate a1s (64 floats/row). 16 lanes x 16B per row (2 rows/warp), packed adds.
// agg1[d] = dinv[d] * (a1s[d] + sum_s a1s[s]).
__global__ void __launch_bounds__(256) k_agg1() {
    int tid = threadIdx.x;
    int hl = tid & 15;
    unsigned hmask = 0xFFFFu << ((tid & 31) & 16);
    int gh = (blockIdx.x * blockDim.x + tid) >> 4;
    int nh = (gridDim.x * blockDim.x) >> 4;
    const ulonglong2* a2 = (const ulonglong2*)g_a1s;   // 16 x 16B per row
    float4* o4 = (float4*)g_agg1;
    for (int row = gh; row < N_NODES; row += nh) {
        int c = g_cnti[row];
        int deg = min(c, CAP);
        float di = rsqrtf((float)c + 1.0f);
        const int* bkt = g_bucket + (size_t)row * CAP;
        ulonglong2 acc = a2[(size_t)row * 16 + hl];
        int e = 0;
        while (e < deg) {
            int n = min(16, deg - e);
            int myidx = (hl < n) ? bkt[e + hl] : 0;
            e += n;
            int j = 0;
            for (; j + 4 <= n; j += 4) {
                int s0 = __shfl_sync(hmask, myidx, j, 16);
                int s1 = __shfl_sync(hmask, myidx, j + 1, 16);
                int s2 = __shfl_sync(hmask, myidx, j + 2, 16);
                int s3 = __shfl_sync(hmask, myidx, j + 3, 16);
                ulonglong2 v0 = a2[(size_t)s0 * 16 + hl];
                ulonglong2 v1 = a2[(size_t)s1 * 16 + hl];
                ulonglong2 v2 = a2[(size_t)s2 * 16 + hl];
                ulonglong2 v3 = a2[(size_t)s3 * 16 + hl];
                ADD_F32X2(acc.x, acc.x, v0.x); ADD_F32X2(acc.y, acc.y, v0.y);
                ADD_F32X2(acc.x, acc.x, v1.x); ADD_F32X2(acc.y, acc.y, v1.y);
                ADD_F32X2(acc.x, acc.x, v2.x); ADD_F32X2(acc.y, acc.y, v2.y);
                ADD_F32X2(acc.x, acc.x, v3.x); ADD_F32X2(acc.y, acc.y, v3.y);
            }
            for (; j < n; j++) {
                int s = __shfl_sync(hmask, myidx, j, 16);
                ulonglong2 v = a2[(size_t)s * 16 + hl];
                ADD_F32X2(acc.x, acc.x, v.x);
                ADD_F32X2(acc.y, acc.y, v.y);
            }
        }
        float2 lo = unpack2(acc.x), hi = unpack2(acc.y);
        o4[(size_t)row * 16 + hl] =
            make_float4(lo.x * di, lo.y * di, hi.x * di, hi.y * di);
    }
}

// out2 = agg1 @ W2 via packed f32x2 (2 rows at once), fused BN2 stats.
__global__ void __launch_bounds__(128) k_gemm2b(const float* __restrict__ W2) {
    int tx = threadIdx.x;
    float w2[F1];
#pragma unroll
    for (int k = 0; k < F1; k++) w2[k] = W2[(size_t)k * F2 + tx];

    __shared__ float2 a_s[F1];   // .x = row r, .y = row r+1
    float lsum = 0.f, lsq = 0.f;

    for (int r = blockIdx.x * 2; r < N_NODES; r += gridDim.x * 2) {
        int lr = tx >> 6;
        int kk = tx & 63;
        int rr = r + lr;
        float av = (rr < N_NODES) ? g_agg1[(size_t)rr * F1 + kk] : 0.f;
        __syncthreads();
        if (lr == 0) a_s[kk].x = av; else a_s[kk].y = av;
        __syncthreads();

        unsigned long long accp = 0ULL;  // packed (0.f, 0.f)
        const unsigned long long* ap = (const unsigned long long*)a_s;
#pragma unroll
        for (int k = 0; k < F1; k++) {
            unsigned long long wp;
            asm("mov.b64 %0, {%1, %1};" : "=l"(wp) : "r"(__float_as_uint(w2[k])));
            FMA_F32X2(accp, ap[k], wp, accp);
        }
        float2 a01 = unpack2(accp);
        float acc0 = a01.x, acc1 = a01.y;

        g_out2[(size_t)r * F2 + tx] = acc0;
        lsum += acc0; lsq += acc0 * acc0;
        if (r + 1 < N_NODES) {
            g_out2[(size_t)(r + 1) * F2 + tx] = acc1;
            lsum += acc1; lsq += acc1 * acc1;
        }
    }
    atomicAdd(&g_sum2[tx], lsum);
    atomicAdd(&g_sq2[tx], lsq);
}

// Fused pool + MLP head: one block per graph. batch is sorted, so graph g's
// node range is found by binary search — no atomics, no g_pool buffer.
__global__ void __launch_bounds__(128) k_poolmlp(
    const int* __restrict__ batch,
    const float* __restrict__ gam, const float* __restrict__ bet,
    const float* __restrict__ fW1, const float* __restrict__ fb1,
    const float* __restrict__ fW2, const float* __restrict__ fb2,
    float* __restrict__ out) {
    int g = blockIdx.x;
    int tx = threadIdx.x;  // 0..127 feature
    // BN2 params for my feature
    float mu = g_sum2[tx] * (1.0f / N_NODES);
    float var = g_sq2[tx] * (1.0f / N_NODES) - mu * mu;
    float sc = gam[tx] * rsqrtf(var + BN_EPS);
    float sh = bet[tx] - mu * sc;

    int lo = lower_bound_batch(batch, g);
    int hi = lower_bound_batch(batch, g + 1);

    float acc = 0.f;
    for (int r = lo; r < hi; r++) {
        float v = g_out2[(size_t)r * F2 + tx];
        acc += fmaxf(v * sc + sh, 0.f);
    }
    float cnt = fmaxf((float)(hi - lo), 1.0f);
    __shared__ float prow[F2];
    __shared__ float partial[2];
    prow[tx] = acc / cnt;
    __syncthreads();

    if (tx < 64) {
        float h = fb1[tx];
#pragma unroll 8
        for (int k = 0; k < F2; k++) h += prow[k] * fW1[(size_t)k * 64 + tx];
        h = fmaxf(h, 0.f);
        float p = h * fW2[tx];
#pragma unroll
        for (int off = 16; off; off >>= 1) p += __shfl_down_sync(0xffffffffu, p, off);
        if ((tx & 31) == 0) partial[tx >> 5] = p;
    }
    __syncthreads();
    if (tx == 0) out[g] = partial[0] + partial[1] + fb2[0];
}

// ------------------------- launch --------------------------------------------
extern "C" void kernel_launch(void* const* d_in, const int* in_sizes, int n_in,
                              void* d_out, int out_size) {
    const float* x   = (const float*)d_in[0];
    const int*   src = (const int*)d_in[1];
    const int*   dst = (const int*)d_in[2];
    const int*   bat = (const int*)d_in[3];
    const float* W1  = (const float*)d_in[4];
    // d_in[5] = b1 (cancels in BN)
    const float* g1  = (const float*)d_in[6];
    const float* be1 = (const float*)d_in[7];
    const float* W2  = (const float*)d_in[8];
    // d_in[9] = b2 (cancels in BN)
    const float* g2  = (const float*)d_in[10];
    const float* be2 = (const float*)d_in[11];
    const float* fW1 = (const float*)d_in[12];
    const float* fb1 = (const float*)d_in[13];
    const float* fW2 = (const float*)d_in[14];
    const float* fb2 = (const float*)d_in[15];
    float* out = (float*)d_out;

    int E = in_sizes[1];

    k_zero<<<512, 256>>>();
    {
        int nthr = (E >> 2) + 1;
        k_fill<<<(nthr + 255) / 256, 256>>>(src, dst, E);
    }
    k_prep<<<(N_NODES + 255) / 256, 256>>>(x);

    k_aggx<<<888, 256>>>();
    k_gemm1b<<<1024, dim3(64, 4)>>>(W1);
    k_mid<<<2048, 256>>>(g1, be1);

    k_agg1<<<888, 256>>>();
    k_gemm2b<<<2048, 128>>>(W2);

    k_poolmlp<<<N_GRAPHS, 128>>>(bat, g2, be2, fW1, fb1, fW2, fb2, out);
}

// round 15
// speedup vs baseline: 1.2284x; 1.0105x over previous
#include <cuda_runtime.h>
#include <cuda_bf16.h>
#include <cstdint>

#define N_NODES 100000
#define N_GRAPHS 2000
#define CAP 128            // per-node bucket capacity (deg ~ Poisson(32), max ~66)
#define F1 64
#define F2 128
#define BN_EPS 1e-5f

// ------------------------- device scratch (no allocs allowed) ---------------
// NOTE: zero-initialized at module load; per-replay resets are relocated into
// k_prep (BN sums) and k_gemm2b (cnti) at provably race-free points.
__device__ int   g_cnti[N_NODES];
__device__ int   g_bucket[(size_t)N_NODES * CAP];
__device__ float g_dinv[N_NODES];
__device__ __align__(16) float g_xs[(size_t)N_NODES * 16];    // x * dinv, padded 10->16
__device__ __align__(16) float g_aggx[(size_t)N_NODES * 16];  // aggregated xs
__device__ __align__(16) float g_out1[(size_t)N_NODES * F1];  // conv1 output (pre-BN)
__device__ __align__(16) float g_a1s[(size_t)N_NODES * F1];   // relu(bn(conv1)) * dinv
__device__ __align__(16) float g_agg1[(size_t)N_NODES * F1];  // aggregated a1s
__device__ __align__(16) float g_out2[(size_t)N_NODES * F2];  // conv2 output (pre-BN)
__device__ float g_sum1[F1], g_sq1[F1];
__device__ float g_sum2[F2], g_sq2[F2];

#define FMA_F32X2(d, a, b, c) \
    asm("fma.rn.f32x2 %0, %1, %2, %3;" : "=l"(d) : "l"(a), "l"(b), "l"(c))
#define ADD_F32X2(d, a, b) \
    asm("add.rn.f32x2 %0, %1, %2;" : "=l"(d) : "l"(a), "l"(b))

__device__ __forceinline__ float2 unpack2(unsigned long long p) {
    unsigned int lo, hi;
    asm("mov.b64 {%0, %1}, %2;" : "=r"(lo), "=r"(hi) : "l"(p));
    return make_float2(__uint_as_float(lo), __uint_as_float(hi));
}

// first index i in [0,N_NODES) with batch[i] >= key (batch sorted ascending)
__device__ __forceinline__ int lower_bound_batch(const int* __restrict__ batch, int key) {
    int lo = 0, hi = N_NODES;
    while (lo < hi) {
        int mid = (lo + hi) >> 1;
        if (batch[mid] < key) lo = mid + 1; else hi = mid;
    }
    return lo;
}

// ------------------------- kernels ------------------------------------------

// Direct bucket fill, 4 edges/thread for MLP on the ATOMG+store chains.
// cnti was zeroed by k_gemm2b of the previous replay (or is zero-initialized).
__global__ void k_fill(const int* __restrict__ src, const int* __restrict__ dst, int E) {
    int i = blockIdx.x * blockDim.x + threadIdx.x;
    int E4 = E >> 2;
    if (i < E4) {
        int4 s = ((const int4*)src)[i];
        int4 d = ((const int4*)dst)[i];
        int p0 = atomicAdd(&g_cnti[d.x], 1);
        int p1 = atomicAdd(&g_cnti[d.y], 1);
        int p2 = atomicAdd(&g_cnti[d.z], 1);
        int p3 = atomicAdd(&g_cnti[d.w], 1);
        if (p0 < CAP) g_bucket[(size_t)d.x * CAP + p0] = s.x;
        if (p1 < CAP) g_bucket[(size_t)d.y * CAP + p1] = s.y;
        if (p2 < CAP) g_bucket[(size_t)d.z * CAP + p2] = s.z;
        if (p3 < CAP) g_bucket[(size_t)d.w * CAP + p3] = s.w;
    } else if (i == E4) {  // tail (E % 4 edges)
        for (int j = E4 * 4; j < E; j++) {
            int d = dst[j];
            int p = atomicAdd(&g_cnti[d], 1);
            if (p < CAP) g_bucket[(size_t)d * CAP + p] = src[j];
        }
    }
}

// dinv + xs = x*dinv (padded to 16 floats). Block 0 also resets the BN sums
// (safe: runs after previous replay's consumers, before this replay's producers).
__global__ void k_prep(const float* __restrict__ x) {
    if (blockIdx.x == 0) {
        int t = threadIdx.x;
        if (t < F1) { g_sum1[t] = 0.f; g_sq1[t] = 0.f; }
        if (t < F2) { g_sum2[t] = 0.f; g_sq2[t] = 0.f; }
    }
    int r = blockIdx.x * blockDim.x + threadIdx.x;
    if (r >= N_NODES) return;
    float di = rsqrtf((float)g_cnti[r] + 1.0f);
    g_dinv[r] = di;
    const float* xr = x + (size_t)r * 10;
    float4* o = (float4*)(g_xs + (size_t)r * 16);
    o[0] = make_float4(xr[0] * di, xr[1] * di, xr[2] * di, xr[3] * di);
    o[1] = make_float4(xr[4] * di, xr[5] * di, xr[6] * di, xr[7] * di);
    o[2] = make_float4(xr[8] * di, xr[9] * di, 0.f, 0.f);
    o[3] = make_float4(0.f, 0.f, 0.f, 0.f);
}

// Aggregate xs (16 floats/row). 4 lanes x 16B per row (8 rows/warp), packed adds.
__global__ void __launch_bounds__(256) k_aggx() {
    int tid = threadIdx.x;
    int ql = tid & 3;
    unsigned qmask = 0xFu << ((tid & 31) & ~3);
    int gq = (blockIdx.x * blockDim.x + tid) >> 2;
    int nq = (gridDim.x * blockDim.x) >> 2;
    const ulonglong2* xs2 = (const ulonglong2*)g_xs;   // 4 x 16B per row
    float4* ag4 = (float4*)g_aggx;
    for (int row = gq; row < N_NODES; row += nq) {
        int c = g_cnti[row];
        int deg = min(c, CAP);
        float di = rsqrtf((float)c + 1.0f);
        const int* bkt = g_bucket + (size_t)row * CAP;
        ulonglong2 acc = xs2[(size_t)row * 4 + ql];
        int e = 0;
        for (; e + 4 <= deg; e += 4) {
            int myidx = bkt[e + ql];
            int s0 = __shfl_sync(qmask, myidx, 0, 4);
            int s1 = __shfl_sync(qmask, myidx, 1, 4);
            int s2 = __shfl_sync(qmask, myidx, 2, 4);
            int s3 = __shfl_sync(qmask, myidx, 3, 4);
            ulonglong2 v0 = xs2[(size_t)s0 * 4 + ql];
            ulonglong2 v1 = xs2[(size_t)s1 * 4 + ql];
            ulonglong2 v2 = xs2[(size_t)s2 * 4 + ql];
            ulonglong2 v3 = xs2[(size_t)s3 * 4 + ql];
            ADD_F32X2(acc.x, acc.x, v0.x); ADD_F32X2(acc.y, acc.y, v0.y);
            ADD_F32X2(acc.x, acc.x, v1.x); ADD_F32X2(acc.y, acc.y, v1.y);
            ADD_F32X2(acc.x, acc.x, v2.x); ADD_F32X2(acc.y, acc.y, v2.y);
            ADD_F32X2(acc.x, acc.x, v3.x); ADD_F32X2(acc.y, acc.y, v3.y);
        }
        if (e < deg) {
            int n = deg - e;
            int myidx = (ql < n) ? bkt[e + ql] : 0;
            for (int j = 0; j < n; j++) {
                int s = __shfl_sync(qmask, myidx, j, 4);
                ulonglong2 v = xs2[(size_t)s * 4 + ql];
                ADD_F32X2(acc.x, acc.x, v.x);
                ADD_F32X2(acc.y, acc.y, v.y);
            }
        }
        float2 lo = unpack2(acc.x), hi = unpack2(acc.y);
        ag4[(size_t)row * 4 + ql] =
            make_float4(lo.x * di, lo.y * di, hi.x * di, hi.y * di);
    }
}

// out1 = aggx[:, :10] @ W1, fused BN1 stats. Block: 64 (features) x 4 (rows),
// 8 rows per iteration (2 per ty) to halve sync overhead.
__global__ void __launch_bounds__(256) k_gemm1b(const float* __restrict__ W1) {
    __shared__ float Ws[10 * F1];
    __shared__ float xs[8][16];
    __shared__ float s_sum[F1], s_sq[F1];
    int tx = threadIdx.x;  // 0..63 feature
    int ty = threadIdx.y;  // 0..3
    int t = ty * 64 + tx;
    for (int j = t; j < 10 * F1; j += 256) Ws[j] = W1[j];
    if (t < F1) { s_sum[t] = 0.f; s_sq[t] = 0.f; }
    __syncthreads();
    float lsum = 0.f, lsq = 0.f;
    for (int rb = blockIdx.x * 8; rb < N_NODES; rb += gridDim.x * 8) {
        if (t < 128) {
            int rr = rb + (t >> 4);
            xs[t >> 4][t & 15] = (rr < N_NODES) ? g_aggx[(size_t)rr * 16 + (t & 15)] : 0.f;
        }
        __syncthreads();
        int row0 = rb + ty;
        int row1 = rb + ty + 4;
        float acc0 = 0.f, acc1 = 0.f;
#pragma unroll
        for (int k = 0; k < 10; k++) {
            float w = Ws[k * F1 + tx];
            acc0 += xs[ty][k] * w;
            acc1 += xs[ty + 4][k] * w;
        }
        if (row0 < N_NODES) {
            g_out1[(size_t)row0 * F1 + tx] = acc0;
            lsum += acc0; lsq += acc0 * acc0;
        }
        if (row1 < N_NODES) {
            g_out1[(size_t)row1 * F1 + tx] = acc1;
            lsum += acc1; lsq += acc1 * acc1;
        }
        __syncthreads();
    }
    atomicAdd(&s_sum[tx], lsum);
    atomicAdd(&s_sq[tx], lsq);
    __syncthreads();
    if (t < F1) {
        atomicAdd(&g_sum1[t], s_sum[t]);
        atomicAdd(&g_sq1[t], s_sq[t]);
    }
}

// a1s = relu(bn1(out1)) * dinv. Elementwise, float4-vectorized.
__global__ void __launch_bounds__(256) k_mid(const float* __restrict__ gam,
                                             const float* __restrict__ bet) {
    __shared__ float sc[F1], sh[F1];
    int tid = threadIdx.x;
    if (tid < F1) {
        float mu = g_sum1[tid] * (1.0f / N_NODES);
        float var = g_sq1[tid] * (1.0f / N_NODES) - mu * mu;
        float s = gam[tid] * rsqrtf(var + BN_EPS);
        sc[tid] = s;
        sh[tid] = bet[tid] - mu * s;
    }
    __syncthreads();
    const float4* in = (const float4*)g_out1;
    float4* outp = (float4*)g_a1s;
    int total = N_NODES * F1 / 4;
    for (int i = blockIdx.x * blockDim.x + tid; i < total; i += gridDim.x * blockDim.x) {
        int row = i >> 4;           // 16 float4 per row
        int f = (i & 15) * 4;
        float di = g_dinv[row];
        float4 v = in[i];
        float4 o;
        o.x = fmaxf(v.x * sc[f + 0] + sh[f + 0], 0.f) * di;
        o.y = fmaxf(v.y * sc[f + 1] + sh[f + 1], 0.f) * di;
        o.z = fmaxf(v.z * sc[f + 2] + sh[f + 2], 0.f) * di;
        o.w = fmaxf(v.w * sc[f + 3] + sh[f + 3], 0.f) * di;
        outp[i] = o;
    }
}

// Aggregate a1s (64 floats/row). 16 lanes x 16B per row (2 rows/warp), packed adds.
// agg1[d] = dinv[d] * (a1s[d] + sum_s a1s[s]).
__global__ void __launch_bounds__(256) k_agg1() {
    int tid = threadIdx.x;
    int hl = tid & 15;
    unsigned hmask = 0xFFFFu << ((tid & 31) & 16);
    int gh = (blockIdx.x * blockDim.x + tid) >> 4;
    int nh = (gridDim.x * blockDim.x) >> 4;
    const ulonglong2* a2 = (const ulonglong2*)g_a1s;   // 16 x 16B per row
    float4* o4 = (float4*)g_agg1;
    for (int row = gh; row < N_NODES; row += nh) {
        int c = g_cnti[row];
        int deg = min(c, CAP);
        float di = rsqrtf((float)c + 1.0f);
        const int* bkt = g_bucket + (size_t)row * CAP;
        ulonglong2 acc = a2[(size_t)row * 16 + hl];
        int e = 0;
        while (e < deg) {
            int n = min(16, deg - e);
            int myidx = (hl < n) ? bkt[e + hl] : 0;
            e += n;
            int j = 0;
            for (; j + 4 <= n; j += 4) {
                int s0 = __shfl_sync(hmask, myidx, j, 16);
                int s1 = __shfl_sync(hmask, myidx, j + 1, 16);
                int s2 = __shfl_sync(hmask, myidx, j + 2, 16);
                int s3 = __shfl_sync(hmask, myidx, j + 3, 16);
                ulonglong2 v0 = a2[(size_t)s0 * 16 + hl];
                ulonglong2 v1 = a2[(size_t)s1 * 16 + hl];
                ulonglong2 v2 = a2[(size_t)s2 * 16 + hl];
                ulonglong2 v3 = a2[(size_t)s3 * 16 + hl];
                ADD_F32X2(acc.x, acc.x, v0.x); ADD_F32X2(acc.y, acc.y, v0.y);
                ADD_F32X2(acc.x, acc.x, v1.x); ADD_F32X2(acc.y, acc.y, v1.y);
                ADD_F32X2(acc.x, acc.x, v2.x); ADD_F32X2(acc.y, acc.y, v2.y);
                ADD_F32X2(acc.x, acc.x, v3.x); ADD_F32X2(acc.y, acc.y, v3.y);
            }
            for (; j < n; j++) {
                int s = __shfl_sync(hmask, myidx, j, 16);
                ulonglong2 v = a2[(size_t)s * 16 + hl];
                ADD_F32X2(acc.x, acc.x, v.x);
                ADD_F32X2(acc.y, acc.y, v.y);
            }
        }
        float2 lo = unpack2(acc.x), hi = unpack2(acc.y);
        o4[(size_t)row * 16 + hl] =
            make_float4(lo.x * di, lo.y * di, hi.x * di, hi.y * di);
    }
}

// out2 = agg1 @ W2 via packed f32x2, 4 rows per iteration, fused BN2 stats.
// Also zeroes cnti for the next replay (agg1 was the last cnti consumer).
__global__ void __launch_bounds__(128) k_gemm2b(const float* __restrict__ W2) {
    int tx = threadIdx.x;
    for (int j = blockIdx.x * blockDim.x + tx; j < N_NODES; j += gridDim.x * blockDim.x)
        g_cnti[j] = 0;

    float w2[F1];
#pragma unroll
    for (int k = 0; k < F1; k++) w2[k] = W2[(size_t)k * F2 + tx];

    __shared__ float4 a_s[F1];   // (row r, r+1, r+2, r+3) per k
    float lsum = 0.f, lsq = 0.f;

    for (int r = blockIdx.x * 4; r < N_NODES; r += gridDim.x * 4) {
        int lr = tx >> 6;       // 0: rows r,r+1 ; 1: rows r+2,r+3
        int kk = tx & 63;
        int ra = r + lr * 2;
        int rb = ra + 1;
        float va = (ra < N_NODES) ? g_agg1[(size_t)ra * F1 + kk] : 0.f;
        float vb = (rb < N_NODES) ? g_agg1[(size_t)rb * F1 + kk] : 0.f;
        __syncthreads();
        if (lr == 0) { a_s[kk].x = va; a_s[kk].y = vb; }
        else         { a_s[kk].z = va; a_s[kk].w = vb; }
        __syncthreads();

        unsigned long long acc01 = 0ULL, acc23 = 0ULL;
        const ulonglong2* ap = (const ulonglong2*)a_s;
#pragma unroll
        for (int k = 0; k < F1; k++) {
            unsigned long long wp;
            asm("mov.b64 %0, {%1, %1};" : "=l"(wp) : "r"(__float_as_uint(w2[k])));
            ulonglong2 av = ap[k];
            FMA_F32X2(acc01, av.x, wp, acc01);
            FMA_F32X2(acc23, av.y, wp, acc23);
        }
        float2 a01 = unpack2(acc01);
        float2 a23 = unpack2(acc23);
        float vr[4] = {a01.x, a01.y, a23.x, a23.y};
#pragma unroll
        for (int q = 0; q < 4; q++) {
            int row = r + q;
            if (row < N_NODES) {
                g_out2[(size_t)row * F2 + tx] = vr[q];
                lsum += vr[q]; lsq += vr[q] * vr[q];
            }
        }
    }
    atomicAdd(&g_sum2[tx], lsum);
    atomicAdd(&g_sq2[tx], lsq);
}

// Fused pool + MLP head: one block per graph. batch is sorted, so graph g's
// node range is found by binary search — no atomics, no g_pool buffer.
__global__ void __launch_bounds__(128) k_poolmlp(
    const int* __restrict__ batch,
    const float* __restrict__ gam, const float* __restrict__ bet,
    const float* __restrict__ fW1, const float* __restrict__ fb1,
    const float* __restrict__ fW2, const float* __restrict__ fb2,
    float* __restrict__ out) {
    int g = blockIdx.x;
    int tx = threadIdx.x;  // 0..127 feature
    // BN2 params for my feature
    float mu = g_sum2[tx] * (1.0f / N_NODES);
    float var = g_sq2[tx] * (1.0f / N_NODES) - mu * mu;
    float sc = gam[tx] * rsqrtf(var + BN_EPS);
    float sh = bet[tx] - mu * sc;

    int lo = lower_bound_batch(batch, g);
    int hi = lower_bound_batch(batch, g + 1);

    float acc = 0.f;
    for (int r = lo; r < hi; r++) {
        float v = g_out2[(size_t)r * F2 + tx];
        acc += fmaxf(v * sc + sh, 0.f);
    }
    float cnt = fmaxf((float)(hi - lo), 1.0f);
    __shared__ float prow[F2];
    __shared__ float partial[2];
    prow[tx] = acc / cnt;
    __syncthreads();

    if (tx < 64) {
        float h = fb1[tx];
#pragma unroll 8
        for (int k = 0; k < F2; k++) h += prow[k] * fW1[(size_t)k * 64 + tx];
        h = fmaxf(h, 0.f);
        float p = h * fW2[tx];
#pragma unroll
        for (int off = 16; off; off >>= 1) p += __shfl_down_sync(0xffffffffu, p, off);
        if ((tx & 31) == 0) partial[tx >> 5] = p;
    }
    __syncthreads();
    if (tx == 0) out[g] = partial[0] + partial[1] + fb2[0];
}

// ------------------------- launch --------------------------------------------
extern "C" void kernel_launch(void* const* d_in, const int* in_sizes, int n_in,
                              void* d_out, int out_size) {
    const float* x   = (const float*)d_in[0];
    const int*   src = (const int*)d_in[1];
    const int*   dst = (const int*)d_in[2];
    const int*   bat = (const int*)d_in[3];
    const float* W1  = (const float*)d_in[4];
    // d_in[5] = b1 (cancels in BN)
    const float* g1  = (const float*)d_in[6];
    const float* be1 = (const float*)d_in[7];
    const float* W2  = (const float*)d_in[8];
    // d_in[9] = b2 (cancels in BN)
    const float* g2  = (const float*)d_in[10];
    const float* be2 = (const float*)d_in[11];
    const float* fW1 = (const float*)d_in[12];
    const float* fb1 = (const float*)d_in[13];
    const float* fW2 = (const float*)d_in[14];
    const float* fb2 = (const float*)d_in[15];
    float* out = (float*)d_out;

    int E = in_sizes[1];

    {
        int nthr = (E >> 2) + 1;
        k_fill<<<(nthr + 255) / 256, 256>>>(src, dst, E);
    }
    k_prep<<<(N_NODES + 255) / 256, 256>>>(x);

    k_aggx<<<888, 256>>>();
    k_gemm1b<<<1024, dim3(64, 4)>>>(W1);
    k_mid<<<2048, 256>>>(g1, be1);

    k_agg1<<<888, 256>>>();
    k_gemm2b<<<2048, 128>>>(W2);

    k_poolmlp<<<N_GRAPHS, 128>>>(bat, g2, be2, fW1, fb1, fW2, fb2, out);
}

// round 16
// speedup vs baseline: 1.2482x; 1.0161x over previous
#include <cuda_runtime.h>
#include <cuda_bf16.h>
#include <cstdint>

#define N_NODES 100000
#define N_GRAPHS 2000
#define CAP 128            // per-node bucket capacity (deg ~ Poisson(32), max ~66)
#define F1 64
#define F2 128
#define BN_EPS 1e-5f

// ------------------------- device scratch (no allocs allowed) ---------------
// NOTE: zero-initialized at module load; per-replay resets are relocated into
// k_prep (BN sums) and k_gemm2b (cnti) at provably race-free points.
__device__ int   g_cnti[N_NODES];
__device__ int   g_bucket[(size_t)N_NODES * CAP];
__device__ float g_dinv[N_NODES];
__device__ __align__(16) float g_xs[(size_t)N_NODES * 16];    // x * dinv, padded 10->16
__device__ __align__(16) float g_aggx[(size_t)N_NODES * 16];  // aggregated xs
__device__ __align__(16) float g_out1[(size_t)N_NODES * F1];  // conv1 output (pre-BN)
__device__ __align__(16) float g_a1s[(size_t)N_NODES * F1];   // relu(bn(conv1)) * dinv
__device__ __align__(16) float g_agg1[(size_t)N_NODES * F1];  // aggregated a1s
__device__ __align__(16) float g_out2[(size_t)N_NODES * F2];  // conv2 output (pre-BN)
__device__ float g_sum1[F1], g_sq1[F1];
__device__ float g_sum2[F2], g_sq2[F2];

#define FMA_F32X2(d, a, b, c) \
    asm("fma.rn.f32x2 %0, %1, %2, %3;" : "=l"(d) : "l"(a), "l"(b), "l"(c))
#define ADD_F32X2(d, a, b) \
    asm("add.rn.f32x2 %0, %1, %2;" : "=l"(d) : "l"(a), "l"(b))

__device__ __forceinline__ float2 unpack2(unsigned long long p) {
    unsigned int lo, hi;
    asm("mov.b64 {%0, %1}, %2;" : "=r"(lo), "=r"(hi) : "l"(p));
    return make_float2(__uint_as_float(lo), __uint_as_float(hi));
}

// first index i in [0,N_NODES) with batch[i] >= key (batch sorted ascending)
__device__ __forceinline__ int lower_bound_batch(const int* __restrict__ batch, int key) {
    int lo = 0, hi = N_NODES;
    while (lo < hi) {
        int mid = (lo + hi) >> 1;
        if (batch[mid] < key) lo = mid + 1; else hi = mid;
    }
    return lo;
}

// ------------------------- kernels ------------------------------------------

// Direct bucket fill, 8 edges/thread for MLP on the ATOMG+store chains.
// cnti was zeroed by k_gemm2b of the previous replay (or is zero-initialized).
__global__ void k_fill(const int* __restrict__ src, const int* __restrict__ dst, int E) {
    int i = blockIdx.x * blockDim.x + threadIdx.x;
    int E8 = E >> 3;
    if (i < E8) {
        const int4* s4 = (const int4*)src;
        const int4* d4 = (const int4*)dst;
        int4 sa = s4[2 * i], sb = s4[2 * i + 1];
        int4 da = d4[2 * i], db = d4[2 * i + 1];
        int p0 = atomicAdd(&g_cnti[da.x], 1);
        int p1 = atomicAdd(&g_cnti[da.y], 1);
        int p2 = atomicAdd(&g_cnti[da.z], 1);
        int p3 = atomicAdd(&g_cnti[da.w], 1);
        int p4 = atomicAdd(&g_cnti[db.x], 1);
        int p5 = atomicAdd(&g_cnti[db.y], 1);
        int p6 = atomicAdd(&g_cnti[db.z], 1);
        int p7 = atomicAdd(&g_cnti[db.w], 1);
        if (p0 < CAP) g_bucket[(size_t)da.x * CAP + p0] = sa.x;
        if (p1 < CAP) g_bucket[(size_t)da.y * CAP + p1] = sa.y;
        if (p2 < CAP) g_bucket[(size_t)da.z * CAP + p2] = sa.z;
        if (p3 < CAP) g_bucket[(size_t)da.w * CAP + p3] = sa.w;
        if (p4 < CAP) g_bucket[(size_t)db.x * CAP + p4] = sb.x;
        if (p5 < CAP) g_bucket[(size_t)db.y * CAP + p5] = sb.y;
        if (p6 < CAP) g_bucket[(size_t)db.z * CAP + p6] = sb.z;
        if (p7 < CAP) g_bucket[(size_t)db.w * CAP + p7] = sb.w;
    } else if (i == E8) {  // tail (E % 8 edges)
        for (int j = E8 * 8; j < E; j++) {
            int d = dst[j];
            int p = atomicAdd(&g_cnti[d], 1);
            if (p < CAP) g_bucket[(size_t)d * CAP + p] = src[j];
        }
    }
}

// dinv + xs = x*dinv (padded to 16 floats). Block 0 also resets the BN sums
// (safe: runs after previous replay's consumers, before this replay's producers).
__global__ void k_prep(const float* __restrict__ x) {
    if (blockIdx.x == 0) {
        int t = threadIdx.x;
        if (t < F1) { g_sum1[t] = 0.f; g_sq1[t] = 0.f; }
        if (t < F2) { g_sum2[t] = 0.f; g_sq2[t] = 0.f; }
    }
    int r = blockIdx.x * blockDim.x + threadIdx.x;
    if (r >= N_NODES) return;
    float di = rsqrtf((float)g_cnti[r] + 1.0f);
    g_dinv[r] = di;
    const float* xr = x + (size_t)r * 10;
    float4* o = (float4*)(g_xs + (size_t)r * 16);
    o[0] = make_float4(xr[0] * di, xr[1] * di, xr[2] * di, xr[3] * di);
    o[1] = make_float4(xr[4] * di, xr[5] * di, xr[6] * di, xr[7] * di);
    o[2] = make_float4(xr[8] * di, xr[9] * di, 0.f, 0.f);
    o[3] = make_float4(0.f, 0.f, 0.f, 0.f);
}

// Aggregate xs (16 floats/row). 4 lanes x 16B per row (8 rows/warp), packed adds.
__global__ void __launch_bounds__(256) k_aggx() {
    int tid = threadIdx.x;
    int ql = tid & 3;
    unsigned qmask = 0xFu << ((tid & 31) & ~3);
    int gq = (blockIdx.x * blockDim.x + tid) >> 2;
    int nq = (gridDim.x * blockDim.x) >> 2;
    const ulonglong2* xs2 = (const ulonglong2*)g_xs;   // 4 x 16B per row
    float4* ag4 = (float4*)g_aggx;
    for (int row = gq; row < N_NODES; row += nq) {
        int c = g_cnti[row];
        int deg = min(c, CAP);
        float di = rsqrtf((float)c + 1.0f);
        const int* bkt = g_bucket + (size_t)row * CAP;
        ulonglong2 acc = xs2[(size_t)row * 4 + ql];
        int e = 0;
        for (; e + 4 <= deg; e += 4) {
            int myidx = bkt[e + ql];
            int s0 = __shfl_sync(qmask, myidx, 0, 4);
            int s1 = __shfl_sync(qmask, myidx, 1, 4);
            int s2 = __shfl_sync(qmask, myidx, 2, 4);
            int s3 = __shfl_sync(qmask, myidx, 3, 4);
            ulonglong2 v0 = xs2[(size_t)s0 * 4 + ql];
            ulonglong2 v1 = xs2[(size_t)s1 * 4 + ql];
            ulonglong2 v2 = xs2[(size_t)s2 * 4 + ql];
            ulonglong2 v3 = xs2[(size_t)s3 * 4 + ql];
            ADD_F32X2(acc.x, acc.x, v0.x); ADD_F32X2(acc.y, acc.y, v0.y);
            ADD_F32X2(acc.x, acc.x, v1.x); ADD_F32X2(acc.y, acc.y, v1.y);
            ADD_F32X2(acc.x, acc.x, v2.x); ADD_F32X2(acc.y, acc.y, v2.y);
            ADD_F32X2(acc.x, acc.x, v3.x); ADD_F32X2(acc.y, acc.y, v3.y);
        }
        if (e < deg) {
            int n = deg - e;
            int myidx = (ql < n) ? bkt[e + ql] : 0;
            for (int j = 0; j < n; j++) {
                int s = __shfl_sync(qmask, myidx, j, 4);
                ulonglong2 v = xs2[(size_t)s * 4 + ql];
                ADD_F32X2(acc.x, acc.x, v.x);
                ADD_F32X2(acc.y, acc.y, v.y);
            }
        }
        float2 lo = unpack2(acc.x), hi = unpack2(acc.y);
        ag4[(size_t)row * 4 + ql] =
            make_float4(lo.x * di, lo.y * di, hi.x * di, hi.y * di);
    }
}

// out1 = aggx[:, :10] @ W1, fused BN1 stats. 16 rows per block-iteration
// (4 rows per ty) to quarter the sync cadence.
__global__ void __launch_bounds__(256) k_gemm1b(const float* __restrict__ W1) {
    __shared__ float Ws[10 * F1];
    __shared__ float xs[16][16];
    __shared__ float s_sum[F1], s_sq[F1];
    int tx = threadIdx.x;  // 0..63 feature
    int ty = threadIdx.y;  // 0..3
    int t = ty * 64 + tx;
    for (int j = t; j < 10 * F1; j += 256) Ws[j] = W1[j];
    if (t < F1) { s_sum[t] = 0.f; s_sq[t] = 0.f; }
    __syncthreads();
    float lsum = 0.f, lsq = 0.f;
    for (int rb = blockIdx.x * 16; rb < N_NODES; rb += gridDim.x * 16) {
        {
            int rr = rb + (t >> 4);
            xs[t >> 4][t & 15] = (rr < N_NODES) ? g_aggx[(size_t)rr * 16 + (t & 15)] : 0.f;
        }
        __syncthreads();
        float acc[4] = {0.f, 0.f, 0.f, 0.f};
#pragma unroll
        for (int k = 0; k < 10; k++) {
            float w = Ws[k * F1 + tx];
            acc[0] += xs[ty][k] * w;
            acc[1] += xs[ty + 4][k] * w;
            acc[2] += xs[ty + 8][k] * w;
            acc[3] += xs[ty + 12][k] * w;
        }
#pragma unroll
        for (int q = 0; q < 4; q++) {
            int row = rb + ty + 4 * q;
            if (row < N_NODES) {
                g_out1[(size_t)row * F1 + tx] = acc[q];
                lsum += acc[q]; lsq += acc[q] * acc[q];
            }
        }
        __syncthreads();
    }
    atomicAdd(&s_sum[tx], lsum);
    atomicAdd(&s_sq[tx], lsq);
    __syncthreads();
    if (t < F1) {
        atomicAdd(&g_sum1[t], s_sum[t]);
        atomicAdd(&g_sq1[t], s_sq[t]);
    }
}

// a1s = relu(bn1(out1)) * dinv. Elementwise, float4-vectorized.
__global__ void __launch_bounds__(256) k_mid(const float* __restrict__ gam,
                                             const float* __restrict__ bet) {
    __shared__ float sc[F1], sh[F1];
    int tid = threadIdx.x;
    if (tid < F1) {
        float mu = g_sum1[tid] * (1.0f / N_NODES);
        float var = g_sq1[tid] * (1.0f / N_NODES) - mu * mu;
        float s = gam[tid] * rsqrtf(var + BN_EPS);
        sc[tid] = s;
        sh[tid] = bet[tid] - mu * s;
    }
    __syncthreads();
    const float4* in = (const float4*)g_out1;
    float4* outp = (float4*)g_a1s;
    int total = N_NODES * F1 / 4;
    for (int i = blockIdx.x * blockDim.x + tid; i < total; i += gridDim.x * blockDim.x) {
        int row = i >> 4;           // 16 float4 per row
        int f = (i & 15) * 4;
        float di = g_dinv[row];
        float4 v = in[i];
        float4 o;
        o.x = fmaxf(v.x * sc[f + 0] + sh[f + 0], 0.f) * di;
        o.y = fmaxf(v.y * sc[f + 1] + sh[f + 1], 0.f) * di;
        o.z = fmaxf(v.z * sc[f + 2] + sh[f + 2], 0.f) * di;
        o.w = fmaxf(v.w * sc[f + 3] + sh[f + 3], 0.f) * di;
        outp[i] = o;
    }
}

// Aggregate a1s (64 floats/row). 16 lanes x 16B per row (2 rows/warp), packed adds.
// agg1[d] = dinv[d] * (a1s[d] + sum_s a1s[s]).
__global__ void __launch_bounds__(256) k_agg1() {
    int tid = threadIdx.x;
    int hl = tid & 15;
    unsigned hmask = 0xFFFFu << ((tid & 31) & 16);
    int gh = (blockIdx.x * blockDim.x + tid) >> 4;
    int nh = (gridDim.x * blockDim.x) >> 4;
    const ulonglong2* a2 = (const ulonglong2*)g_a1s;   // 16 x 16B per row
    float4* o4 = (float4*)g_agg1;
    for (int row = gh; row < N_NODES; row += nh) {
        int c = g_cnti[row];
        int deg = min(c, CAP);
        float di = rsqrtf((float)c + 1.0f);
        const int* bkt = g_bucket + (size_t)row * CAP;
        ulonglong2 acc = a2[(size_t)row * 16 + hl];
        int e = 0;
        while (e < deg) {
            int n = min(16, deg - e);
            int myidx = (hl < n) ? bkt[e + hl] : 0;
            e += n;
            int j = 0;
            for (; j + 4 <= n; j += 4) {
                int s0 = __shfl_sync(hmask, myidx, j, 16);
                int s1 = __shfl_sync(hmask, myidx, j + 1, 16);
                int s2 = __shfl_sync(hmask, myidx, j + 2, 16);
                int s3 = __shfl_sync(hmask, myidx, j + 3, 16);
                ulonglong2 v0 = a2[(size_t)s0 * 16 + hl];
                ulonglong2 v1 = a2[(size_t)s1 * 16 + hl];
                ulonglong2 v2 = a2[(size_t)s2 * 16 + hl];
                ulonglong2 v3 = a2[(size_t)s3 * 16 + hl];
                ADD_F32X2(acc.x, acc.x, v0.x); ADD_F32X2(acc.y, acc.y, v0.y);
                ADD_F32X2(acc.x, acc.x, v1.x); ADD_F32X2(acc.y, acc.y, v1.y);
                ADD_F32X2(acc.x, acc.x, v2.x); ADD_F32X2(acc.y, acc.y, v2.y);
                ADD_F32X2(acc.x, acc.x, v3.x); ADD_F32X2(acc.y, acc.y, v3.y);
            }
            for (; j < n; j++) {
                int s = __shfl_sync(hmask, myidx, j, 16);
                ulonglong2 v = a2[(size_t)s * 16 + hl];
                ADD_F32X2(acc.x, acc.x, v.x);
                ADD_F32X2(acc.y, acc.y, v.y);
            }
        }
        float2 lo = unpack2(acc.x), hi = unpack2(acc.y);
        o4[(size_t)row * 16 + hl] =
            make_float4(lo.x * di, lo.y * di, hi.x * di, hi.y * di);
    }
}

// out2 = agg1 @ W2 via packed f32x2, 4 rows per iteration, fused BN2 stats.
// Also zeroes cnti for the next replay (agg1 was the last cnti consumer).
__global__ void __launch_bounds__(128) k_gemm2b(const float* __restrict__ W2) {
    int tx = threadIdx.x;
    for (int j = blockIdx.x * blockDim.x + tx; j < N_NODES; j += gridDim.x * blockDim.x)
        g_cnti[j] = 0;

    float w2[F1];
#pragma unroll
    for (int k = 0; k < F1; k++) w2[k] = W2[(size_t)k * F2 + tx];

    __shared__ float4 a_s[F1];   // (row r, r+1, r+2, r+3) per k
    float lsum = 0.f, lsq = 0.f;

    for (int r = blockIdx.x * 4; r < N_NODES; r += gridDim.x * 4) {
        int lr = tx >> 6;       // 0: rows r,r+1 ; 1: rows r+2,r+3
        int kk = tx & 63;
        int ra = r + lr * 2;
        int rb = ra + 1;
        float va = (ra < N_NODES) ? g_agg1[(size_t)ra * F1 + kk] : 0.f;
        float vb = (rb < N_NODES) ? g_agg1[(size_t)rb * F1 + kk] : 0.f;
        __syncthreads();
        if (lr == 0) { a_s[kk].x = va; a_s[kk].y = vb; }
        else         { a_s[kk].z = va; a_s[kk].w = vb; }
        __syncthreads();

        unsigned long long acc01 = 0ULL, acc23 = 0ULL;
        const ulonglong2* ap = (const ulonglong2*)a_s;
#pragma unroll
        for (int k = 0; k < F1; k++) {
            unsigned long long wp;
            asm("mov.b64 %0, {%1, %1};" : "=l"(wp) : "r"(__float_as_uint(w2[k])));
            ulonglong2 av = ap[k];
            FMA_F32X2(acc01, av.x, wp, acc01);
            FMA_F32X2(acc23, av.y, wp, acc23);
        }
        float2 a01 = unpack2(acc01);
        float2 a23 = unpack2(acc23);
        float vr[4] = {a01.x, a01.y, a23.x, a23.y};
#pragma unroll
        for (int q = 0; q < 4; q++) {
            int row = r + q;
            if (row < N_NODES) {
                g_out2[(size_t)row * F2 + tx] = vr[q];
                lsum += vr[q]; lsq += vr[q] * vr[q];
            }
        }
    }
    atomicAdd(&g_sum2[tx], lsum);
    atomicAdd(&g_sq2[tx], lsq);
}

// Fused pool + MLP head: one block per graph. batch is sorted, so graph g's
// node range is found by binary search — no atomics, no g_pool buffer.
__global__ void __launch_bounds__(128) k_poolmlp(
    const int* __restrict__ batch,
    const float* __restrict__ gam, const float* __restrict__ bet,
    const float* __restrict__ fW1, const float* __restrict__ fb1,
    const float* __restrict__ fW2, const float* __restrict__ fb2,
    float* __restrict__ out) {
    int g = blockIdx.x;
    int tx = threadIdx.x;  // 0..127 feature
    // BN2 params for my feature
    float mu = g_sum2[tx] * (1.0f / N_NODES);
    float var = g_sq2[tx] * (1.0f / N_NODES) - mu * mu;
    float sc = gam[tx] * rsqrtf(var + BN_EPS);
    float sh = bet[tx] - mu * sc;

    int lo = lower_bound_batch(batch, g);
    int hi = lower_bound_batch(batch, g + 1);

    float acc = 0.f;
    for (int r = lo; r < hi; r++) {
        float v = g_out2[(size_t)r * F2 + tx];
        acc += fmaxf(v * sc + sh, 0.f);
    }
    float cnt = fmaxf((float)(hi - lo), 1.0f);
    __shared__ float prow[F2];
    __shared__ float partial[2];
    prow[tx] = acc / cnt;
    __syncthreads();

    if (tx < 64) {
        float h = fb1[tx];
#pragma unroll 8
        for (int k = 0; k < F2; k++) h += prow[k] * fW1[(size_t)k * 64 + tx];
        h = fmaxf(h, 0.f);
        float p = h * fW2[tx];
#pragma unroll
        for (int off = 16; off; off >>= 1) p += __shfl_down_sync(0xffffffffu, p, off);
        if ((tx & 31) == 0) partial[tx >> 5] = p;
    }
    __syncthreads();
    if (tx == 0) out[g] = partial[0] + partial[1] + fb2[0];
}

// ------------------------- launch --------------------------------------------
extern "C" void kernel_launch(void* const* d_in, const int* in_sizes, int n_in,
                              void* d_out, int out_size) {
    const float* x   = (const float*)d_in[0];
    const int*   src = (const int*)d_in[1];
    const int*   dst = (const int*)d_in[2];
    const int*   bat = (const int*)d_in[3];
    const float* W1  = (const float*)d_in[4];
    // d_in[5] = b1 (cancels in BN)
    const float* g1  = (const float*)d_in[6];
    const float* be1 = (const float*)d_in[7];
    const float* W2  = (const float*)d_in[8];
    // d_in[9] = b2 (cancels in BN)
    const float* g2  = (const float*)d_in[10];
    const float* be2 = (const float*)d_in[11];
    const float* fW1 = (const float*)d_in[12];
    const float* fb1 = (const float*)d_in[13];
    const float* fW2 = (const float*)d_in[14];
    const float* fb2 = (const float*)d_in[15];
    float* out = (float*)d_out;

    int E = in_sizes[1];

    {
        int nthr = (E >> 3) + 1;
        k_fill<<<(nthr + 255) / 256, 256>>>(src, dst, E);
    }
    k_prep<<<(N_NODES + 255) / 256, 256>>>(x);

    k_aggx<<<888, 256>>>();
    k_gemm1b<<<1024, dim3(64, 4)>>>(W1);
    k_mid<<<2048, 256>>>(g1, be1);

    k_agg1<<<888, 256>>>();
    k_gemm2b<<<2048, 128>>>(W2);

    k_poolmlp<<<N_GRAPHS, 128>>>(bat, g2, be2, fW1, fb1, fW2, fb2, out);
}

// round 17
// speedup vs baseline: 1.2517x; 1.0028x over previous
#include <cuda_runtime.h>
#include <cuda_bf16.h>
#include <cstdint>

#define N_NODES 100000
#define N_GRAPHS 2000
#define CAP 128            // per-node bucket capacity (deg ~ Poisson(32), max ~66)
#define F1 64
#define F2 128
#define BN_EPS 1e-5f

// ------------------------- device scratch (no allocs allowed) ---------------
// NOTE: zero-initialized at module load; per-replay resets are relocated into
// k_prep (BN sums) and k_gemm2b (cnti) at provably race-free points.
__device__ int   g_cnti[N_NODES];
__device__ int   g_bucket[(size_t)N_NODES * CAP];
__device__ float g_dinv[N_NODES];
__device__ __align__(16) float g_xs[(size_t)N_NODES * 16];    // x * dinv, padded 10->16
__device__ __align__(16) float g_aggx[(size_t)N_NODES * 16];  // aggregated xs
__device__ __align__(16) float g_out1[(size_t)N_NODES * F1];  // conv1 output (pre-BN)
// a1s = relu(bn1(out1)) * dinv stored as bf16x2 (32 words = 128B per row)
__device__ __align__(16) unsigned int g_a1b[(size_t)N_NODES * 32];
__device__ __align__(16) float g_agg1[(size_t)N_NODES * F1];  // aggregated a1s (fp32)
__device__ __align__(16) float g_out2[(size_t)N_NODES * F2];  // conv2 output (pre-BN)
__device__ float g_sum1[F1], g_sq1[F1];
__device__ float g_sum2[F2], g_sq2[F2];

#define FMA_F32X2(d, a, b, c) \
    asm("fma.rn.f32x2 %0, %1, %2, %3;" : "=l"(d) : "l"(a), "l"(b), "l"(c))
#define ADD_F32X2(d, a, b) \
    asm("add.rn.f32x2 %0, %1, %2;" : "=l"(d) : "l"(a), "l"(b))

__device__ __forceinline__ float2 unpack2(unsigned long long p) {
    unsigned int lo, hi;
    asm("mov.b64 {%0, %1}, %2;" : "=r"(lo), "=r"(hi) : "l"(p));
    return make_float2(__uint_as_float(lo), __uint_as_float(hi));
}

// bf16x2 word -> packed f32x2 (exact: bf16 = truncated fp32). low bf16 -> low f32.
__device__ __forceinline__ unsigned long long bfpair(unsigned int u) {
    unsigned long long p;
    asm("mov.b64 %0, {%1, %2};" : "=l"(p) : "r"(u << 16), "r"(u & 0xFFFF0000u));
    return p;
}

// first index i in [0,N_NODES) with batch[i] >= key (batch sorted ascending)
__device__ __forceinline__ int lower_bound_batch(const int* __restrict__ batch, int key) {
    int lo = 0, hi = N_NODES;
    while (lo < hi) {
        int mid = (lo + hi) >> 1;
        if (batch[mid] < key) lo = mid + 1; else hi = mid;
    }
    return lo;
}

// ------------------------- kernels ------------------------------------------

// Direct bucket fill, 8 edges/thread for MLP on the ATOMG+store chains.
__global__ void k_fill(const int* __restrict__ src, const int* __restrict__ dst, int E) {
    int i = blockIdx.x * blockDim.x + threadIdx.x;
    int E8 = E >> 3;
    if (i < E8) {
        const int4* s4 = (const int4*)src;
        const int4* d4 = (const int4*)dst;
        int4 sa = s4[2 * i], sb = s4[2 * i + 1];
        int4 da = d4[2 * i], db = d4[2 * i + 1];
        int p0 = atomicAdd(&g_cnti[da.x], 1);
        int p1 = atomicAdd(&g_cnti[da.y], 1);
        int p2 = atomicAdd(&g_cnti[da.z], 1);
        int p3 = atomicAdd(&g_cnti[da.w], 1);
        int p4 = atomicAdd(&g_cnti[db.x], 1);
        int p5 = atomicAdd(&g_cnti[db.y], 1);
        int p6 = atomicAdd(&g_cnti[db.z], 1);
        int p7 = atomicAdd(&g_cnti[db.w], 1);
        if (p0 < CAP) g_bucket[(size_t)da.x * CAP + p0] = sa.x;
        if (p1 < CAP) g_bucket[(size_t)da.y * CAP + p1] = sa.y;
        if (p2 < CAP) g_bucket[(size_t)da.z * CAP + p2] = sa.z;
        if (p3 < CAP) g_bucket[(size_t)da.w * CAP + p3] = sa.w;
        if (p4 < CAP) g_bucket[(size_t)db.x * CAP + p4] = sb.x;
        if (p5 < CAP) g_bucket[(size_t)db.y * CAP + p5] = sb.y;
        if (p6 < CAP) g_bucket[(size_t)db.z * CAP + p6] = sb.z;
        if (p7 < CAP) g_bucket[(size_t)db.w * CAP + p7] = sb.w;
    } else if (i == E8) {  // tail (E % 8 edges)
        for (int j = E8 * 8; j < E; j++) {
            int d = dst[j];
            int p = atomicAdd(&g_cnti[d], 1);
            if (p < CAP) g_bucket[(size_t)d * CAP + p] = src[j];
        }
    }
}

// dinv + xs = x*dinv (padded to 16 floats). Block 0 also resets the BN sums.
__global__ void k_prep(const float* __restrict__ x) {
    if (blockIdx.x == 0) {
        int t = threadIdx.x;
        if (t < F1) { g_sum1[t] = 0.f; g_sq1[t] = 0.f; }
        if (t < F2) { g_sum2[t] = 0.f; g_sq2[t] = 0.f; }
    }
    int r = blockIdx.x * blockDim.x + threadIdx.x;
    if (r >= N_NODES) return;
    float di = rsqrtf((float)g_cnti[r] + 1.0f);
    g_dinv[r] = di;
    const float* xr = x + (size_t)r * 10;
    float4* o = (float4*)(g_xs + (size_t)r * 16);
    o[0] = make_float4(xr[0] * di, xr[1] * di, xr[2] * di, xr[3] * di);
    o[1] = make_float4(xr[4] * di, xr[5] * di, xr[6] * di, xr[7] * di);
    o[2] = make_float4(xr[8] * di, xr[9] * di, 0.f, 0.f);
    o[3] = make_float4(0.f, 0.f, 0.f, 0.f);
}

// Aggregate xs (16 floats/row). 4 lanes x 16B per row (8 rows/warp), packed adds.
__global__ void __launch_bounds__(256) k_aggx() {
    int tid = threadIdx.x;
    int ql = tid & 3;
    unsigned qmask = 0xFu << ((tid & 31) & ~3);
    int gq = (blockIdx.x * blockDim.x + tid) >> 2;
    int nq = (gridDim.x * blockDim.x) >> 2;
    const ulonglong2* xs2 = (const ulonglong2*)g_xs;   // 4 x 16B per row
    float4* ag4 = (float4*)g_aggx;
    for (int row = gq; row < N_NODES; row += nq) {
        int c = g_cnti[row];
        int deg = min(c, CAP);
        float di = rsqrtf((float)c + 1.0f);
        const int* bkt = g_bucket + (size_t)row * CAP;
        ulonglong2 acc = xs2[(size_t)row * 4 + ql];
        int e = 0;
        for (; e + 4 <= deg; e += 4) {
            int myidx = bkt[e + ql];
            int s0 = __shfl_sync(qmask, myidx, 0, 4);
            int s1 = __shfl_sync(qmask, myidx, 1, 4);
            int s2 = __shfl_sync(qmask, myidx, 2, 4);
            int s3 = __shfl_sync(qmask, myidx, 3, 4);
            ulonglong2 v0 = xs2[(size_t)s0 * 4 + ql];
            ulonglong2 v1 = xs2[(size_t)s1 * 4 + ql];
            ulonglong2 v2 = xs2[(size_t)s2 * 4 + ql];
            ulonglong2 v3 = xs2[(size_t)s3 * 4 + ql];
            ADD_F32X2(acc.x, acc.x, v0.x); ADD_F32X2(acc.y, acc.y, v0.y);
            ADD_F32X2(acc.x, acc.x, v1.x); ADD_F32X2(acc.y, acc.y, v1.y);
            ADD_F32X2(acc.x, acc.x, v2.x); ADD_F32X2(acc.y, acc.y, v2.y);
            ADD_F32X2(acc.x, acc.x, v3.x); ADD_F32X2(acc.y, acc.y, v3.y);
        }
        if (e < deg) {
            int n = deg - e;
            int myidx = (ql < n) ? bkt[e + ql] : 0;
            for (int j = 0; j < n; j++) {
                int s = __shfl_sync(qmask, myidx, j, 4);
                ulonglong2 v = xs2[(size_t)s * 4 + ql];
                ADD_F32X2(acc.x, acc.x, v.x);
                ADD_F32X2(acc.y, acc.y, v.y);
            }
        }
        float2 lo = unpack2(acc.x), hi = unpack2(acc.y);
        ag4[(size_t)row * 4 + ql] =
            make_float4(lo.x * di, lo.y * di, hi.x * di, hi.y * di);
    }
}

// out1 = aggx[:, :10] @ W1, fused BN1 stats. 16 rows per block-iteration.
__global__ void __launch_bounds__(256) k_gemm1b(const float* __restrict__ W1) {
    __shared__ float Ws[10 * F1];
    __shared__ float xs[16][16];
    __shared__ float s_sum[F1], s_sq[F1];
    int tx = threadIdx.x;  // 0..63 feature
    int ty = threadIdx.y;  // 0..3
    int t = ty * 64 + tx;
    for (int j = t; j < 10 * F1; j += 256) Ws[j] = W1[j];
    if (t < F1) { s_sum[t] = 0.f; s_sq[t] = 0.f; }
    __syncthreads();
    float lsum = 0.f, lsq = 0.f;
    for (int rb = blockIdx.x * 16; rb < N_NODES; rb += gridDim.x * 16) {
        {
            int rr = rb + (t >> 4);
            xs[t >> 4][t & 15] = (rr < N_NODES) ? g_aggx[(size_t)rr * 16 + (t & 15)] : 0.f;
        }
        __syncthreads();
        float acc[4] = {0.f, 0.f, 0.f, 0.f};
#pragma unroll
        for (int k = 0; k < 10; k++) {
            float w = Ws[k * F1 + tx];
            acc[0] += xs[ty][k] * w;
            acc[1] += xs[ty + 4][k] * w;
            acc[2] += xs[ty + 8][k] * w;
            acc[3] += xs[ty + 12][k] * w;
        }
#pragma unroll
        for (int q = 0; q < 4; q++) {
            int row = rb + ty + 4 * q;
            if (row < N_NODES) {
                g_out1[(size_t)row * F1 + tx] = acc[q];
                lsum += acc[q]; lsq += acc[q] * acc[q];
            }
        }
        __syncthreads();
    }
    atomicAdd(&s_sum[tx], lsum);
    atomicAdd(&s_sq[tx], lsq);
    __syncthreads();
    if (t < F1) {
        atomicAdd(&g_sum1[t], s_sum[t]);
        atomicAdd(&g_sq1[t], s_sq[t]);
    }
}

// a1b = bf16(relu(bn1(out1)) * dinv). Elementwise, float4 in / uint2 out.
__global__ void __launch_bounds__(256) k_mid(const float* __restrict__ gam,
                                             const float* __restrict__ bet) {
    __shared__ float sc[F1], sh[F1];
    int tid = threadIdx.x;
    if (tid < F1) {
        float mu = g_sum1[tid] * (1.0f / N_NODES);
        float var = g_sq1[tid] * (1.0f / N_NODES) - mu * mu;
        float s = gam[tid] * rsqrtf(var + BN_EPS);
        sc[tid] = s;
        sh[tid] = bet[tid] - mu * s;
    }
    __syncthreads();
    const float4* in = (const float4*)g_out1;
    uint2* outp = (uint2*)g_a1b;
    int total = N_NODES * F1 / 4;
    for (int i = blockIdx.x * blockDim.x + tid; i < total; i += gridDim.x * blockDim.x) {
        int row = i >> 4;           // 16 float4 per row
        int f = (i & 15) * 4;
        float di = g_dinv[row];
        float4 v = in[i];
        float o0 = fmaxf(v.x * sc[f + 0] + sh[f + 0], 0.f) * di;
        float o1 = fmaxf(v.y * sc[f + 1] + sh[f + 1], 0.f) * di;
        float o2 = fmaxf(v.z * sc[f + 2] + sh[f + 2], 0.f) * di;
        float o3 = fmaxf(v.w * sc[f + 3] + sh[f + 3], 0.f) * di;
        unsigned int w0, w1;
        asm("cvt.rn.bf16x2.f32 %0, %1, %2;" : "=r"(w0) : "f"(o1), "f"(o0));  // hi=f+1, lo=f
        asm("cvt.rn.bf16x2.f32 %0, %1, %2;" : "=r"(w1) : "f"(o3), "f"(o2));
        outp[i] = make_uint2(w0, w1);
    }
}

// Aggregate a1b (bf16, 128B/row). 8 lanes x LDG.128 per row (4 rows/warp).
// Decode bf16->f32 via shift (exact), accumulate packed fp32.
// agg1[d] = dinv[d] * (a1s[d] + sum_s a1s[s])  (fp32 output).
__global__ void __launch_bounds__(256) k_agg1() {
    int tid = threadIdx.x;
    int ol = tid & 7;
    unsigned omask = 0xFFu << ((tid & 31) & ~7);
    int go = (blockIdx.x * blockDim.x + tid) >> 3;
    int no = (gridDim.x * blockDim.x) >> 3;
    const ulonglong2* a2 = (const ulonglong2*)g_a1b;   // 8 x 16B(bf16) per row
    float4* o4 = (float4*)g_agg1;
    for (int row = go; row < N_NODES; row += no) {
        int c = g_cnti[row];
        int deg = min(c, CAP);
        float di = rsqrtf((float)c + 1.0f);
        const int* bkt = g_bucket + (size_t)row * CAP;
        // init from own row (self loop)
        unsigned long long acc0, acc1, acc2, acc3;
        {
            ulonglong2 v = a2[(size_t)row * 8 + ol];
            unsigned int u0, u1, u2, u3;
            asm("mov.b64 {%0,%1}, %2;" : "=r"(u0), "=r"(u1) : "l"(v.x));
            asm("mov.b64 {%0,%1}, %2;" : "=r"(u2), "=r"(u3) : "l"(v.y));
            acc0 = bfpair(u0); acc1 = bfpair(u1);
            acc2 = bfpair(u2); acc3 = bfpair(u3);
        }
        int e = 0;
        while (e < deg) {
            int n = min(8, deg - e);
            int myidx = (ol < n) ? bkt[e + ol] : 0;
            e += n;
            for (int j = 0; j < n; j++) {
                int s = __shfl_sync(omask, myidx, j, 8);
                ulonglong2 v = a2[(size_t)s * 8 + ol];
                unsigned int u0, u1, u2, u3;
                asm("mov.b64 {%0,%1}, %2;" : "=r"(u0), "=r"(u1) : "l"(v.x));
                asm("mov.b64 {%0,%1}, %2;" : "=r"(u2), "=r"(u3) : "l"(v.y));
                ADD_F32X2(acc0, acc0, bfpair(u0));
                ADD_F32X2(acc1, acc1, bfpair(u1));
                ADD_F32X2(acc2, acc2, bfpair(u2));
                ADD_F32X2(acc3, acc3, bfpair(u3));
            }
        }
        float2 p0 = unpack2(acc0), p1 = unpack2(acc1);
        float2 p2 = unpack2(acc2), p3 = unpack2(acc3);
        // lane ol covers features [ol*8, ol*8+8)
        o4[(size_t)row * 16 + ol * 2 + 0] =
            make_float4(p0.x * di, p0.y * di, p1.x * di, p1.y * di);
        o4[(size_t)row * 16 + ol * 2 + 1] =
            make_float4(p2.x * di, p2.y * di, p3.x * di, p3.y * di);
    }
}

// out2 = agg1 @ W2 via packed f32x2, 4 rows per iteration, fused BN2 stats.
// Also zeroes cnti for the next replay (agg1 was the last cnti consumer).
__global__ void __launch_bounds__(128) k_gemm2b(const float* __restrict__ W2) {
    int tx = threadIdx.x;
    for (int j = blockIdx.x * blockDim.x + tx; j < N_NODES; j += gridDim.x * blockDim.x)
        g_cnti[j] = 0;

    float w2[F1];
#pragma unroll
    for (int k = 0; k < F1; k++) w2[k] = W2[(size_t)k * F2 + tx];

    __shared__ float4 a_s[F1];   // (row r, r+1, r+2, r+3) per k
    float lsum = 0.f, lsq = 0.f;

    for (int r = blockIdx.x * 4; r < N_NODES; r += gridDim.x * 4) {
        int lr = tx >> 6;       // 0: rows r,r+1 ; 1: rows r+2,r+3
        int kk = tx & 63;
        int ra = r + lr * 2;
        int rb = ra + 1;
        float va = (ra < N_NODES) ? g_agg1[(size_t)ra * F1 + kk] : 0.f;
        float vb = (rb < N_NODES) ? g_agg1[(size_t)rb * F1 + kk] : 0.f;
        __syncthreads();
        if (lr == 0) { a_s[kk].x = va; a_s[kk].y = vb; }
        else         { a_s[kk].z = va; a_s[kk].w = vb; }
        __syncthreads();

        unsigned long long acc01 = 0ULL, acc23 = 0ULL;
        const ulonglong2* ap = (const ulonglong2*)a_s;
#pragma unroll
        for (int k = 0; k < F1; k++) {
            unsigned long long wp;
            asm("mov.b64 %0, {%1, %1};" : "=l"(wp) : "r"(__float_as_uint(w2[k])));
            ulonglong2 av = ap[k];
            FMA_F32X2(acc01, av.x, wp, acc01);
            FMA_F32X2(acc23, av.y, wp, acc23);
        }
        float2 a01 = unpack2(acc01);
        float2 a23 = unpack2(acc23);
        float vr[4] = {a01.x, a01.y, a23.x, a23.y};
#pragma unroll
        for (int q = 0; q < 4; q++) {
            int row = r + q;
            if (row < N_NODES) {
                g_out2[(size_t)row * F2 + tx] = vr[q];
                lsum += vr[q]; lsq += vr[q] * vr[q];
            }
        }
    }
    atomicAdd(&g_sum2[tx], lsum);
    atomicAdd(&g_sq2[tx], lsq);
}

// Fused pool + MLP head: one block per graph, binary-search node range.
__global__ void __launch_bounds__(128) k_poolmlp(
    const int* __restrict__ batch,
    const float* __restrict__ gam, const float* __restrict__ bet,
    const float* __restrict__ fW1, const float* __restrict__ fb1,
    const float* __restrict__ fW2, const float* __restrict__ fb2,
    float* __restrict__ out) {
    int g = blockIdx.x;
    int tx = threadIdx.x;  // 0..127 feature
    float mu = g_sum2[tx] * (1.0f / N_NODES);
    float var = g_sq2[tx] * (1.0f / N_NODES) - mu * mu;
    float sc = gam[tx] * rsqrtf(var + BN_EPS);
    float sh = bet[tx] - mu * sc;

    int lo = lower_bound_batch(batch, g);
    int hi = lower_bound_batch(batch, g + 1);

    float acc = 0.f;
    for (int r = lo; r < hi; r++) {
        float v = g_out2[(size_t)r * F2 + tx];
        acc += fmaxf(v * sc + sh, 0.f);
    }
    float cnt = fmaxf((float)(hi - lo), 1.0f);
    __shared__ float prow[F2];
    __shared__ float partial[2];
    prow[tx] = acc / cnt;
    __syncthreads();

    if (tx < 64) {
        float h = fb1[tx];
#pragma unroll 8
        for (int k = 0; k < F2; k++) h += prow[k] * fW1[(size_t)k * 64 + tx];
        h = fmaxf(h, 0.f);
        float p = h * fW2[tx];
#pragma unroll
        for (int off = 16; off; off >>= 1) p += __shfl_down_sync(0xffffffffu, p, off);
        if ((tx & 31) == 0) partial[tx >> 5] = p;
    }
    __syncthreads();
    if (tx == 0) out[g] = partial[0] + partial[1] + fb2[0];
}

// ------------------------- launch --------------------------------------------
extern "C" void kernel_launch(void* const* d_in, const int* in_sizes, int n_in,
                              void* d_out, int out_size) {
    const float* x   = (const float*)d_in[0];
    const int*   src = (const int*)d_in[1];
    const int*   dst = (const int*)d_in[2];
    const int*   bat = (const int*)d_in[3];
    const float* W1  = (const float*)d_in[4];
    // d_in[5] = b1 (cancels in BN)
    const float* g1  = (const float*)d_in[6];
    const float* be1 = (const float*)d_in[7];
    const float* W2  = (const float*)d_in[8];
    // d_in[9] = b2 (cancels in BN)
    const float* g2  = (const float*)d_in[10];
    const float* be2 = (const float*)d_in[11];
    const float* fW1 = (const float*)d_in[12];
    const float* fb1 = (const float*)d_in[13];
    const float* fW2 = (const float*)d_in[14];
    const float* fb2 = (const float*)d_in[15];
    float* out = (float*)d_out;

    int E = in_sizes[1];

    {
        int nthr = (E >> 3) + 1;
        k_fill<<<(nthr + 255) / 256, 256>>>(src, dst, E);
    }
    k_prep<<<(N_NODES + 255) / 256, 256>>>(x);

    k_aggx<<<888, 256>>>();
    k_gemm1b<<<1024, dim3(64, 4)>>>(W1);
    k_mid<<<2048, 256>>>(g1, be1);

    k_agg1<<<888, 256>>>();
    k_gemm2b<<<2048, 128>>>(W2);

    k_poolmlp<<<N_GRAPHS, 128>>>(bat, g2, be2, fW1, fb1, fW2, fb2, out);
}